// round 4
// baseline (speedup 1.0000x reference)
#include <cuda_runtime.h>
#include <cuda_bf16.h>
#include <math.h>

// Problem: B=2, S=2048, D=2048, H=16, hd=128
#define SCALE_QK 0.08838834764831843f  // 1/sqrt(128)

typedef unsigned long long ull;

// ---------------- scratch (device globals: allocation-free) ----------------
__device__ __align__(16) float g_q[2 * 16 * 2048 * 128];     // [b][h][s][d]
__device__ __align__(16) float g_k[2 * 16 * 2048 * 128];
__device__ __align__(16) float g_v[2 * 16 * 2048 * 128];
__device__ __align__(16) float g_attn[4096 * 2048];          // [b*S + s][h*128 + d]
__device__ __align__(16) float g_tab[2048 * 128];            // [s][0..63]=cos, [s][64..127]=sin

// ---------------- f32x2 helpers (B300: FFMA2 = 2x FFMA throughput) ---------
#define FMA2(c, a, b) asm("fma.rn.f32x2 %0, %1, %2, %0;" : "+l"(c) : "l"(a), "l"(b))
#define MUL2(d, a, b) asm("mul.rn.f32x2 %0, %1, %2;" : "=l"(d) : "l"(a), "l"(b))

__device__ __forceinline__ ull pack2(float x, float y) {
    ull r; asm("mov.b64 %0, {%1, %2};" : "=l"(r) : "f"(x), "f"(y)); return r;
}
__device__ __forceinline__ float2 unpack2(ull u) {
    float2 f; asm("mov.b64 {%0, %1}, %2;" : "=f"(f.x), "=f"(f.y) : "l"(u)); return f;
}

// ---------------- RoPE table --------------------------------------------
__global__ void rope_tab_kernel() {
    int idx = blockIdx.x * 256 + threadIdx.x;
    if (idx >= 2048 * 64) return;
    int s = idx >> 6, f = idx & 63;
    double invf = pow(10000.0, -2.0 * (double)f / 128.0);
    double ang = (double)s * invf;
    g_tab[s * 128 + f]      = (float)cos(ang);
    g_tab[s * 128 + 64 + f] = (float)sin(ang);
}

// ---------------- GEMM: C = A @ W^T --------------------------------------
// MODE 1: A = x [4096,2048]; N fused over {wq,wk,wv} (48 N-tiles); epilogue
//         applies RoPE (q,k) and scatters to g_q/g_k/g_v in [b][h][s][d].
// MODE 0: A = g_attn; W = wo; plain store to out [4096,2048].
// Tile 128x128xBK8, 256 threads, 8x8 microtile via fma.rn.f32x2 with
// duplicated-A smem (broadcast pairs via LDS, no packing in mainloop).
template <int MODE>
__global__ __launch_bounds__(256, 2) void gemm_kernel(
    const float* __restrict__ Ain, const float* __restrict__ w0,
    const float* __restrict__ w1, const float* __restrict__ w2,
    float* __restrict__ outp)
{
    __shared__ float Asd[2][8][256];  // duplicated: Asd[k][2m]=Asd[k][2m+1]=A[m][k]
    __shared__ float Bs[2][8][128];

    const int tid = threadIdx.x;
    const int tx = tid & 15, ty = tid >> 4;
    const int lrow = tid >> 1, lc4 = (tid & 1) * 4;
    const int nt = blockIdx.x, mt = blockIdx.y;

    const float* A = (MODE == 0) ? g_attn : Ain;
    const float* W;
    int region = 0, nloc;
    if (MODE == 0) { W = w0; nloc = nt; }
    else {
        region = nt >> 4;
        W = (region == 0) ? w0 : (region == 1) ? w1 : w2;
        nloc = nt & 15;
    }

    const float* Ap = A + (size_t)(mt * 128 + lrow) * 2048 + lc4;
    const float* Bp = W + (size_t)(nloc * 128 + lrow) * 2048 + lc4;

    ull acc[8][4];
#pragma unroll
    for (int i = 0; i < 8; i++)
#pragma unroll
        for (int j = 0; j < 4; j++) acc[i][j] = 0ull;

    // prologue fill buffer 0
    {
        float4 ra = *(const float4*)Ap;
        float4 rb = *(const float4*)Bp;
        *(float2*)&Asd[0][lc4 + 0][2 * lrow] = make_float2(ra.x, ra.x);
        *(float2*)&Asd[0][lc4 + 1][2 * lrow] = make_float2(ra.y, ra.y);
        *(float2*)&Asd[0][lc4 + 2][2 * lrow] = make_float2(ra.z, ra.z);
        *(float2*)&Asd[0][lc4 + 3][2 * lrow] = make_float2(ra.w, ra.w);
        Bs[0][lc4 + 0][lrow] = rb.x;
        Bs[0][lc4 + 1][lrow] = rb.y;
        Bs[0][lc4 + 2][lrow] = rb.z;
        Bs[0][lc4 + 3][lrow] = rb.w;
    }
    __syncthreads();

    int buf = 0;
    for (int kb = 0; kb < 256; ++kb) {
        float4 na, nb;
        if (kb < 255) {
            na = *(const float4*)(Ap + (kb + 1) * 8);
            nb = *(const float4*)(Bp + (kb + 1) * 8);
        }
#pragma unroll
        for (int k = 0; k < 8; ++k) {
            const ull* ap  = (const ull*)&Asd[buf][k][8 * ty];
            const ull* ap2 = (const ull*)&Asd[buf][k][128 + 8 * ty];
            ull a[8];
            a[0] = ap[0];  a[1] = ap[1];  a[2] = ap[2];  a[3] = ap[3];
            a[4] = ap2[0]; a[5] = ap2[1]; a[6] = ap2[2]; a[7] = ap2[3];
            const ull* bp  = (const ull*)&Bs[buf][k][4 * tx];
            const ull* bp2 = (const ull*)&Bs[buf][k][64 + 4 * tx];
            ull b[4];
            b[0] = bp[0]; b[1] = bp[1]; b[2] = bp2[0]; b[3] = bp2[1];
#pragma unroll
            for (int i = 0; i < 8; i++)
#pragma unroll
                for (int j = 0; j < 4; j++) FMA2(acc[i][j], a[i], b[j]);
        }
        if (kb < 255) {
            int nx = buf ^ 1;
            *(float2*)&Asd[nx][lc4 + 0][2 * lrow] = make_float2(na.x, na.x);
            *(float2*)&Asd[nx][lc4 + 1][2 * lrow] = make_float2(na.y, na.y);
            *(float2*)&Asd[nx][lc4 + 2][2 * lrow] = make_float2(na.z, na.z);
            *(float2*)&Asd[nx][lc4 + 3][2 * lrow] = make_float2(na.w, na.w);
            Bs[nx][lc4 + 0][lrow] = nb.x;
            Bs[nx][lc4 + 1][lrow] = nb.y;
            Bs[nx][lc4 + 2][lrow] = nb.z;
            Bs[nx][lc4 + 3][lrow] = nb.w;
            __syncthreads();
            buf = nx;
        }
    }

    // ---- epilogue ----
    if (MODE == 0) {
        float* O = outp + (size_t)(mt * 128) * 2048 + nt * 128;
#pragma unroll
        for (int i = 0; i < 8; i++) {
            int r = (i < 4) ? (ty * 4 + i) : (64 + ty * 4 + (i - 4));
#pragma unroll
            for (int g = 0; g < 2; g++) {
                float2 p0 = unpack2(acc[i][2 * g]);
                float2 p1 = unpack2(acc[i][2 * g + 1]);
                *(float4*)&O[(size_t)r * 2048 + g * 64 + tx * 4] =
                    make_float4(p0.x, p0.y, p1.x, p1.y);
            }
        }
    } else {
        int h = nt & 15;
        float* dst = (region == 0) ? g_q : (region == 1) ? g_k : g_v;
#pragma unroll
        for (int i = 0; i < 8; i++) {
            int r = (i < 4) ? (ty * 4 + i) : (64 + ty * 4 + (i - 4));
            int m = mt * 128 + r;
            int b = m >> 11, s = m & 2047;
            size_t base = ((size_t)(b * 16 + h) * 2048 + s) * 128;
#pragma unroll
            for (int g = 0; g < 2; g++) {
                int cb = g * 64 + tx * 4;
                float2 p0 = unpack2(acc[i][2 * g]);
                float2 p1 = unpack2(acc[i][2 * g + 1]);
                float4 ov;
                if (region < 2) {  // RoPE for q, k
                    int f = cb >> 1;  // = g*32 + tx*2
                    float c0 = g_tab[s * 128 + f],     s0 = g_tab[s * 128 + 64 + f];
                    float c1 = g_tab[s * 128 + f + 1], s1 = g_tab[s * 128 + 64 + f + 1];
                    ov = make_float4(p0.x * c0 - p0.y * s0, p0.x * s0 + p0.y * c0,
                                     p1.x * c1 - p1.y * s1, p1.x * s1 + p1.y * c1);
                } else {
                    ov = make_float4(p0.x, p0.y, p1.x, p1.y);
                }
                *(float4*)&dst[base + cb] = ov;
            }
        }
    }
}

// ---------------- Flash attention (causal, fp32, f32x2) ------------------
// Grid: (bh=32, 32); qt = 31 - blockIdx.y (heavy diagonals first). 256 thr.
// Smem (floats): Qd[128][132] dup-transposed Q; Kt[128][68] transposed K;
//                Vs[64][128]; Pd[64][130] dup probs; alpha[64]; l[64].
#define OFF_QD 0
#define OFF_KT 16896
#define OFF_VS 25600
#define OFF_PD 33792
#define OFF_AL 42112
#define OFF_L  42176
#define ATTN_SMEM_BYTES (42240 * 4)

__global__ __launch_bounds__(256, 1) void attn_kernel() {
    extern __shared__ float sm[];
    float* Qd  = sm + OFF_QD;
    float* Kt  = sm + OFF_KT;
    float* Vs  = sm + OFF_VS;
    float* Pd  = sm + OFF_PD;
    float* sAl = sm + OFF_AL;
    float* sL  = sm + OFF_L;

    const int tid = threadIdx.x;
    const int bh = blockIdx.x;                 // b*16 + h
    const int qt = 31 - blockIdx.y;            // q-tile, heavy first
    const int kx = tid & 15, qy = tid >> 4;    // QK layout: rows qy*4.., cols kx*4..
    const int dvx = kx, iy = qy;               // PV layout: rows iy*4.., dv 4dvx / 64+4dvx

    const size_t bh_off = (size_t)bh * 2048 * 128;
    const float* Qg = g_q + bh_off + (size_t)qt * 64 * 128;

    // load Q -> Qd (transposed + duplicated): Qd[d][2i]=Qd[d][2i+1]=Q[i][d]
#pragma unroll
    for (int t = 0; t < 8; t++) {
        int idx = t * 256 + tid;
        int r = idx >> 5, c4 = (idx & 31) * 4;
        float4 q = *(const float4*)&Qg[r * 128 + c4];
        *(float2*)&Qd[(c4 + 0) * 132 + 2 * r] = make_float2(q.x, q.x);
        *(float2*)&Qd[(c4 + 1) * 132 + 2 * r] = make_float2(q.y, q.y);
        *(float2*)&Qd[(c4 + 2) * 132 + 2 * r] = make_float2(q.z, q.z);
        *(float2*)&Qd[(c4 + 3) * 132 + 2 * r] = make_float2(q.w, q.w);
    }

    ull o2[4][4];
#pragma unroll
    for (int i = 0; i < 4; i++)
#pragma unroll
        for (int j = 0; j < 4; j++) o2[i][j] = 0ull;
    float m_[4], l_[4];
#pragma unroll
    for (int i = 0; i < 4; i++) { m_[i] = -INFINITY; l_[i] = 0.0f; }

    for (int kv = 0; kv <= qt; ++kv) {
        __syncthreads();  // prev tile's QK/PV done with Kt/Vs/Pd
        const float* Kg = g_k + bh_off + (size_t)kv * 64 * 128;
        const float* Vg = g_v + bh_off + (size_t)kv * 64 * 128;
#pragma unroll
        for (int t = 0; t < 8; t++) {
            int idx = t * 256 + tid;
            // K: transpose to Kt[d][j] (stride 68 -> conflict-free STS)
            int j = idx & 63, d4 = idx >> 6;
            float4 kk = *(const float4*)&Kg[j * 128 + d4 * 4];
            Kt[(4 * d4 + 0) * 68 + j] = kk.x;
            Kt[(4 * d4 + 1) * 68 + j] = kk.y;
            Kt[(4 * d4 + 2) * 68 + j] = kk.z;
            Kt[(4 * d4 + 3) * 68 + j] = kk.w;
            // V: natural layout, coalesced float4
            int r = idx >> 5, c4 = (idx & 31) * 4;
            *(float4*)&Vs[r * 128 + c4] = *(const float4*)&Vg[r * 128 + c4];
        }
        __syncthreads();

        // ---- QK^T: vectorized over j via f32x2 ----
        ull s2[4][2];
#pragma unroll
        for (int i = 0; i < 4; i++) { s2[i][0] = 0ull; s2[i][1] = 0ull; }
#pragma unroll 4
        for (int d = 0; d < 128; ++d) {
            const ulonglong2* qp = (const ulonglong2*)&Qd[d * 132 + 8 * qy];
            ulonglong2 qa = qp[0], qb = qp[1];
            ulonglong2 kk = *(const ulonglong2*)&Kt[d * 68 + 4 * kx];
            FMA2(s2[0][0], qa.x, kk.x); FMA2(s2[0][1], qa.x, kk.y);
            FMA2(s2[1][0], qa.y, kk.x); FMA2(s2[1][1], qa.y, kk.y);
            FMA2(s2[2][0], qb.x, kk.x); FMA2(s2[2][1], qb.x, kk.y);
            FMA2(s2[3][0], qb.y, kk.x); FMA2(s2[3][1], qb.y, kk.y);
        }

        // ---- online softmax (rows owned in QK layout, 16-lane reductions) ----
        const bool diag = (kv == qt);
        float sv[4][4];
#pragma unroll
        for (int ii = 0; ii < 4; ii++) {
            float2 p0 = unpack2(s2[ii][0]);
            float2 p1 = unpack2(s2[ii][1]);
            sv[ii][0] = p0.x; sv[ii][1] = p0.y; sv[ii][2] = p1.x; sv[ii][3] = p1.y;
        }
#pragma unroll
        for (int ii = 0; ii < 4; ii++) {
            int i = qy * 4 + ii;
#pragma unroll
            for (int jj = 0; jj < 4; jj++) {
                float s = sv[ii][jj] * SCALE_QK;
                if (diag && (kx * 4 + jj) > i) s = -1e30f;
                sv[ii][jj] = s;
            }
            float mx = fmaxf(fmaxf(sv[ii][0], sv[ii][1]), fmaxf(sv[ii][2], sv[ii][3]));
#pragma unroll
            for (int off = 8; off > 0; off >>= 1)
                mx = fmaxf(mx, __shfl_xor_sync(0xffffffffu, mx, off));
            float mn = fmaxf(m_[ii], mx);
            float al = __expf(m_[ii] - mn);
            m_[ii] = mn;
            float rs = 0.0f;
#pragma unroll
            for (int jj = 0; jj < 4; jj++) {
                float p = __expf(sv[ii][jj] - mn);
                sv[ii][jj] = p;
                rs += p;
            }
#pragma unroll
            for (int off = 8; off > 0; off >>= 1)
                rs += __shfl_xor_sync(0xffffffffu, rs, off);
            l_[ii] = l_[ii] * al + rs;
#pragma unroll
            for (int jj = 0; jj < 4; jj++)
                *(float2*)&Pd[(kx * 4 + jj) * 130 + 2 * i] =
                    make_float2(sv[ii][jj], sv[ii][jj]);
            if (kx == 0) sAl[i] = al;
        }
        __syncthreads();

        // ---- P @ V: vectorized over dv via f32x2 ----
#pragma unroll
        for (int ii = 0; ii < 4; ii++) {
            float a = sAl[iy * 4 + ii];
            ull av = pack2(a, a);
#pragma unroll
            for (int p = 0; p < 4; p++) MUL2(o2[ii][p], o2[ii][p], av);
        }
#pragma unroll 2
        for (int j = 0; j < 64; ++j) {
            const ull* pp = (const ull*)&Pd[j * 130 + 8 * iy];
            ull p0 = pp[0], p1 = pp[1], p2 = pp[2], p3 = pp[3];
            ulonglong2 v0 = *(const ulonglong2*)&Vs[j * 128 + 4 * dvx];
            ulonglong2 v1 = *(const ulonglong2*)&Vs[j * 128 + 64 + 4 * dvx];
            FMA2(o2[0][0], p0, v0.x); FMA2(o2[0][1], p0, v0.y);
            FMA2(o2[0][2], p0, v1.x); FMA2(o2[0][3], p0, v1.y);
            FMA2(o2[1][0], p1, v0.x); FMA2(o2[1][1], p1, v0.y);
            FMA2(o2[1][2], p1, v1.x); FMA2(o2[1][3], p1, v1.y);
            FMA2(o2[2][0], p2, v0.x); FMA2(o2[2][1], p2, v0.y);
            FMA2(o2[2][2], p2, v1.x); FMA2(o2[2][3], p2, v1.y);
            FMA2(o2[3][0], p3, v0.x); FMA2(o2[3][1], p3, v0.y);
            FMA2(o2[3][2], p3, v1.x); FMA2(o2[3][3], p3, v1.y);
        }
    }

    // ---- finalize: divide by l, scatter to g_attn [b*S+s][h*128+dv] ----
    if (kx == 0) {
#pragma unroll
        for (int ii = 0; ii < 4; ii++) sL[qy * 4 + ii] = l_[ii];
    }
    __syncthreads();
    const int b = bh >> 4, h = bh & 15;
    float* Og = g_attn + (size_t)(b * 2048 + qt * 64) * 2048 + h * 128;
#pragma unroll
    for (int ii = 0; ii < 4; ii++) {
        int i = iy * 4 + ii;
        float inv = 1.0f / sL[i];
#pragma unroll
        for (int g = 0; g < 2; g++) {
            float2 p0 = unpack2(o2[ii][2 * g]);
            float2 p1 = unpack2(o2[ii][2 * g + 1]);
            *(float4*)&Og[(size_t)i * 2048 + g * 64 + 4 * dvx] =
                make_float4(p0.x * inv, p0.y * inv, p1.x * inv, p1.y * inv);
        }
    }
}

// ---------------- launch -------------------------------------------------
extern "C" void kernel_launch(void* const* d_in, const int* in_sizes, int n_in,
                              void* d_out, int out_size) {
    const float* x  = (const float*)d_in[0];
    const float* wq = (const float*)d_in[1];
    const float* wk = (const float*)d_in[2];
    const float* wv = (const float*)d_in[3];
    const float* wo = (const float*)d_in[4];
    float* out = (float*)d_out;

    cudaFuncSetAttribute(attn_kernel, cudaFuncAttributeMaxDynamicSharedMemorySize,
                         ATTN_SMEM_BYTES);

    rope_tab_kernel<<<512, 256>>>();
    gemm_kernel<1><<<dim3(48, 32), 256>>>(x, wq, wk, wv, nullptr);
    attn_kernel<<<dim3(32, 32), 256, ATTN_SMEM_BYTES>>>();
    gemm_kernel<0><<<dim3(16, 32), 256>>>(nullptr, wo, nullptr, nullptr, out);
}

// round 6
// speedup vs baseline: 2.3682x; 2.3682x over previous
#include <cuda_runtime.h>
#include <cuda_bf16.h>
#include <math.h>
#include <stdint.h>

// Problem: B=2, S=2048, D=2048, H=16, hd=128
#define SCALE_QK 0.08838834764831843f  // 1/sqrt(128)

typedef unsigned long long ull;

// ---------------- scratch (device globals: allocation-free) ----------------
__device__ __align__(16) float g_q[2 * 16 * 2048 * 128];     // [b][h][s][d]
__device__ __align__(16) float g_k[2 * 16 * 2048 * 128];
__device__ __align__(16) float g_v[2 * 16 * 2048 * 128];
__device__ __align__(16) float g_attn[4096 * 2048];          // [b*S + s][h*128 + d]
__device__ __align__(16) float g_tab[2048 * 128];            // [s][0..63]=cos, [s][64..127]=sin

// ---------------- PTX helpers ---------------------------------------------
#define FMA2(c, a, b) asm("fma.rn.f32x2 %0, %1, %2, %0;" : "+l"(c) : "l"(a), "l"(b))
#define MUL2(d, a, b) asm("mul.rn.f32x2 %0, %1, %2;" : "=l"(d) : "l"(a), "l"(b))

__device__ __forceinline__ ull pack2(float x, float y) {
    ull r; asm("mov.b64 %0, {%1, %2};" : "=l"(r) : "f"(x), "f"(y)); return r;
}
__device__ __forceinline__ float2 unpack2(ull u) {
    float2 f; asm("mov.b64 {%0, %1}, %2;" : "=f"(f.x), "=f"(f.y) : "l"(u)); return f;
}
__device__ __forceinline__ uint32_t smem_u32(const void* p) {
    uint32_t a;
    asm("{ .reg .u64 t; cvta.to.shared.u64 t, %1; cvt.u32.u64 %0, t; }" : "=r"(a) : "l"(p));
    return a;
}

// ldmatrix x4 (sm_75+, base target OK)
#define LDSM4(r0, r1, r2, r3, addr) \
    asm volatile("ldmatrix.sync.aligned.m8n8.x4.shared.b16 {%0,%1,%2,%3}, [%4];" \
                 : "=r"(r0), "=r"(r1), "=r"(r2), "=r"(r3) : "r"(addr))

// bf16 mma (sm_80+, base target OK): D(16x8,f32) += A(16x16,bf16) x B(16x8,bf16)
#define MMA_BF16(d, a, b) \
    asm volatile("mma.sync.aligned.m16n8k16.row.col.f32.bf16.bf16.f32 " \
                 "{%0,%1,%2,%3}, {%4,%5,%6,%7}, {%8,%9}, {%0,%1,%2,%3};" \
                 : "+f"((d)[0]), "+f"((d)[1]), "+f"((d)[2]), "+f"((d)[3]) \
                 : "r"((a)[0]), "r"((a)[1]), "r"((a)[2]), "r"((a)[3]), \
                   "r"((b)[0]), "r"((b)[1]))

// split a float pair into packed bf16 hi + bf16 lo (2-term decomposition)
__device__ __forceinline__ void split2(float x, float y, uint32_t& hi, uint32_t& lo) {
    __nv_bfloat16 xh = __float2bfloat16_rn(x), yh = __float2bfloat16_rn(y);
    float xr = x - __bfloat162float(xh);
    float yr = y - __bfloat162float(yh);
    __nv_bfloat162 hp; hp.x = xh; hp.y = yh;
    __nv_bfloat162 lp = __floats2bfloat162_rn(xr, yr);
    hi = *(uint32_t*)&hp;
    lo = *(uint32_t*)&lp;
}

// ---------------- RoPE table ----------------------------------------------
__global__ void rope_tab_kernel() {
    int idx = blockIdx.x * 256 + threadIdx.x;
    if (idx >= 2048 * 64) return;
    int s = idx >> 6, f = idx & 63;
    double invf = pow(10000.0, -2.0 * (double)f / 128.0);
    double ang = (double)s * invf;
    g_tab[s * 128 + f]      = (float)cos(ang);
    g_tab[s * 128 + 64 + f] = (float)sin(ang);
}

// ---------------- bf16-split mma.sync GEMM: C = A @ W^T --------------------
// Tile 128x128, BK=16, 128 stages, double-buffered smem, 8 warps (2x4),
// 64x32 per warp, 3 HMMA products per tile pair (hi*hi + hi*lo + lo*hi).
// MODE 1: A = x; nt in [0,48): region -> {wq,wk,wv}, head h = nt&15;
//         epilogue applies RoPE (q,k) and scatters to [b][h][s][d].
// MODE 0: A = g_attn, W = wo, plain store to out.
#define ASTR 24  // bf16 elems per smem row (16 data + 8 pad) = 48 bytes

template <int MODE>
__global__ __launch_bounds__(256, 1) void gemm_mma(
    const float* __restrict__ Ain, const float* __restrict__ w0,
    const float* __restrict__ w1, const float* __restrict__ w2,
    float* __restrict__ outp)
{
    // planes: 0=aHi 1=aLo 2=bHi 3=bLo ; [buf][plane][row*ASTR + k]
    __shared__ __nv_bfloat16 smb[2][4][128 * ASTR];   // 49152 B

    const int tid = threadIdx.x;
    const int wid = tid >> 5, lane = tid & 31;
    const int wm = wid >> 2, wn = wid & 3;
    const int nt = blockIdx.x, mt = blockIdx.y;

    const float* A = (MODE == 0) ? g_attn : Ain;
    const float* W;
    int region = 0, nloc;
    if (MODE == 0) { W = w0; nloc = nt; }
    else {
        region = nt >> 4;
        W = (region == 0) ? w0 : (region == 1) ? w1 : w2;
        nloc = nt & 15;
    }

    // producer mapping: 2 threads per row, 8 fp32 each
    const int prow = tid >> 1, phalf = tid & 1;
    const float* Ap = A + (size_t)(mt * 128 + prow) * 2048 + phalf * 8;
    const float* Bp = W + (size_t)(nloc * 128 + prow) * 2048 + phalf * 8;

    // ldmatrix lane addresses (per buf, per plane)
    uint32_t aAddr[2][2], bAddr[2][2];
#pragma unroll
    for (int bufi = 0; bufi < 2; bufi++)
#pragma unroll
        for (int p = 0; p < 2; p++) {
            aAddr[bufi][p] = smem_u32(&smb[bufi][p][0]) +
                (uint32_t)((wm * 64 + (lane & 15)) * 48 + ((lane >> 4) & 1) * 16);
            bAddr[bufi][p] = smem_u32(&smb[bufi][2 + p][0]) +
                (uint32_t)((wn * 32 + ((lane >> 4) & 1) * 8 + (lane & 7)) * 48 +
                           ((lane >> 3) & 1) * 16);
        }

    float acc[4][4][4];
#pragma unroll
    for (int m = 0; m < 4; m++)
#pragma unroll
        for (int n = 0; n < 4; n++)
#pragma unroll
            for (int e = 0; e < 4; e++) acc[m][n][e] = 0.0f;

    // producer store helper (lambda-free macro-ish)
    float4 ra0, ra1, rb0, rb1;
    ra0 = *(const float4*)(Ap + 0);
    ra1 = *(const float4*)(Ap + 4);
    rb0 = *(const float4*)(Bp + 0);
    rb1 = *(const float4*)(Bp + 4);

#define STORE_STAGE(bufi)                                                       \
    do {                                                                        \
        uint4 h, l;                                                             \
        split2(ra0.x, ra0.y, h.x, l.x); split2(ra0.z, ra0.w, h.y, l.y);         \
        split2(ra1.x, ra1.y, h.z, l.z); split2(ra1.z, ra1.w, h.w, l.w);         \
        *(uint4*)&smb[bufi][0][prow * ASTR + phalf * 8] = h;                    \
        *(uint4*)&smb[bufi][1][prow * ASTR + phalf * 8] = l;                    \
        split2(rb0.x, rb0.y, h.x, l.x); split2(rb0.z, rb0.w, h.y, l.y);         \
        split2(rb1.x, rb1.y, h.z, l.z); split2(rb1.z, rb1.w, h.w, l.w);         \
        *(uint4*)&smb[bufi][2][prow * ASTR + phalf * 8] = h;                    \
        *(uint4*)&smb[bufi][3][prow * ASTR + phalf * 8] = l;                    \
    } while (0)

    STORE_STAGE(0);
    __syncthreads();

    for (int s = 0; s < 128; ++s) {
        const int buf = s & 1;
        if (s < 127) {  // prefetch next stage (LDG latency hidden by mma below)
            ra0 = *(const float4*)(Ap + (s + 1) * 16);
            ra1 = *(const float4*)(Ap + (s + 1) * 16 + 4);
            rb0 = *(const float4*)(Bp + (s + 1) * 16);
            rb1 = *(const float4*)(Bp + (s + 1) * 16 + 4);
        }

        // load fragments
        uint32_t af[2][4][4];   // [plane][mtile][reg]
        uint32_t bfr[2][4][2];  // [plane][ntile][reg]
#pragma unroll
        for (int p = 0; p < 2; p++) {
#pragma unroll
            for (int m = 0; m < 4; m++)
                LDSM4(af[p][m][0], af[p][m][1], af[p][m][2], af[p][m][3],
                      aAddr[buf][p] + (uint32_t)(m * 16 * 48));
#pragma unroll
            for (int g = 0; g < 2; g++) {
                uint32_t r0, r1, r2, r3;
                LDSM4(r0, r1, r2, r3, bAddr[buf][p] + (uint32_t)(g * 16 * 48));
                bfr[p][2 * g][0] = r0; bfr[p][2 * g][1] = r1;
                bfr[p][2 * g + 1][0] = r2; bfr[p][2 * g + 1][1] = r3;
            }
        }

        // 3-product bf16 split MMAs
#pragma unroll
        for (int m = 0; m < 4; m++)
#pragma unroll
            for (int n = 0; n < 4; n++) {
                MMA_BF16(acc[m][n], af[0][m], bfr[0][n]);  // hi*hi
                MMA_BF16(acc[m][n], af[0][m], bfr[1][n]);  // hi*lo
                MMA_BF16(acc[m][n], af[1][m], bfr[0][n]);  // lo*hi
            }

        if (s < 127) STORE_STAGE(buf ^ 1);
        __syncthreads();
    }
#undef STORE_STAGE

    // ---- epilogue ----
    const int qr = lane >> 2, qc = 2 * (lane & 3);
#pragma unroll
    for (int m = 0; m < 4; m++) {
        const int r0 = mt * 128 + wm * 64 + m * 16 + qr;
#pragma unroll
        for (int half = 0; half < 2; half++) {
            const int r = r0 + half * 8;
            float* drow;
            const float* tab = nullptr;
            if (MODE == 0) {
                drow = outp + (size_t)r * 2048 + nt * 128;
            } else {
                const int b = r >> 11, spos = r & 2047, h = nt & 15;
                float* dst = (region == 0) ? g_q : (region == 1) ? g_k : g_v;
                drow = dst + ((size_t)(b * 16 + h) * 2048 + spos) * 128;
                tab = g_tab + spos * 128;
            }
#pragma unroll
            for (int n = 0; n < 4; n++) {
                const int col = wn * 32 + n * 8 + qc;
                float v0 = acc[m][n][2 * half], v1 = acc[m][n][2 * half + 1];
                float2 ov;
                if (MODE == 1 && region < 2) {  // RoPE rotate pair (2f, 2f+1)
                    const int f = col >> 1;
                    float c = tab[f], sn = tab[64 + f];
                    ov = make_float2(v0 * c - v1 * sn, v0 * sn + v1 * c);
                } else {
                    ov = make_float2(v0, v1);
                }
                *(float2*)&drow[col] = ov;
            }
        }
    }
}

// ---------------- Flash attention (causal, fp32, f32x2) — unchanged R4 ----
#define OFF_QD 0
#define OFF_KT 16896
#define OFF_VS 25600
#define OFF_PD 33792
#define OFF_AL 42112
#define OFF_L  42176
#define ATTN_SMEM_BYTES (42240 * 4)

__global__ __launch_bounds__(256, 1) void attn_kernel() {
    extern __shared__ float sm[];
    float* Qd  = sm + OFF_QD;
    float* Kt  = sm + OFF_KT;
    float* Vs  = sm + OFF_VS;
    float* Pd  = sm + OFF_PD;
    float* sAl = sm + OFF_AL;
    float* sL  = sm + OFF_L;

    const int tid = threadIdx.x;
    const int bh = blockIdx.x;
    const int qt = 31 - blockIdx.y;
    const int kx = tid & 15, qy = tid >> 4;
    const int dvx = kx, iy = qy;

    const size_t bh_off = (size_t)bh * 2048 * 128;
    const float* Qg = g_q + bh_off + (size_t)qt * 64 * 128;

#pragma unroll
    for (int t = 0; t < 8; t++) {
        int idx = t * 256 + tid;
        int r = idx >> 5, c4 = (idx & 31) * 4;
        float4 q = *(const float4*)&Qg[r * 128 + c4];
        *(float2*)&Qd[(c4 + 0) * 132 + 2 * r] = make_float2(q.x, q.x);
        *(float2*)&Qd[(c4 + 1) * 132 + 2 * r] = make_float2(q.y, q.y);
        *(float2*)&Qd[(c4 + 2) * 132 + 2 * r] = make_float2(q.z, q.z);
        *(float2*)&Qd[(c4 + 3) * 132 + 2 * r] = make_float2(q.w, q.w);
    }

    ull o2[4][4];
#pragma unroll
    for (int i = 0; i < 4; i++)
#pragma unroll
        for (int j = 0; j < 4; j++) o2[i][j] = 0ull;
    float m_[4], l_[4];
#pragma unroll
    for (int i = 0; i < 4; i++) { m_[i] = -INFINITY; l_[i] = 0.0f; }

    for (int kv = 0; kv <= qt; ++kv) {
        __syncthreads();
        const float* Kg = g_k + bh_off + (size_t)kv * 64 * 128;
        const float* Vg = g_v + bh_off + (size_t)kv * 64 * 128;
#pragma unroll
        for (int t = 0; t < 8; t++) {
            int idx = t * 256 + tid;
            int j = idx & 63, d4 = idx >> 6;
            float4 kk = *(const float4*)&Kg[j * 128 + d4 * 4];
            Kt[(4 * d4 + 0) * 68 + j] = kk.x;
            Kt[(4 * d4 + 1) * 68 + j] = kk.y;
            Kt[(4 * d4 + 2) * 68 + j] = kk.z;
            Kt[(4 * d4 + 3) * 68 + j] = kk.w;
            int r = idx >> 5, c4 = (idx & 31) * 4;
            *(float4*)&Vs[r * 128 + c4] = *(const float4*)&Vg[r * 128 + c4];
        }
        __syncthreads();

        ull s2[4][2];
#pragma unroll
        for (int i = 0; i < 4; i++) { s2[i][0] = 0ull; s2[i][1] = 0ull; }
#pragma unroll 4
        for (int d = 0; d < 128; ++d) {
            const ulonglong2* qp = (const ulonglong2*)&Qd[d * 132 + 8 * qy];
            ulonglong2 qa = qp[0], qb = qp[1];
            ulonglong2 kk = *(const ulonglong2*)&Kt[d * 68 + 4 * kx];
            FMA2(s2[0][0], qa.x, kk.x); FMA2(s2[0][1], qa.x, kk.y);
            FMA2(s2[1][0], qa.y, kk.x); FMA2(s2[1][1], qa.y, kk.y);
            FMA2(s2[2][0], qb.x, kk.x); FMA2(s2[2][1], qb.x, kk.y);
            FMA2(s2[3][0], qb.y, kk.x); FMA2(s2[3][1], qb.y, kk.y);
        }

        const bool diag = (kv == qt);
        float sv[4][4];
#pragma unroll
        for (int ii = 0; ii < 4; ii++) {
            float2 p0 = unpack2(s2[ii][0]);
            float2 p1 = unpack2(s2[ii][1]);
            sv[ii][0] = p0.x; sv[ii][1] = p0.y; sv[ii][2] = p1.x; sv[ii][3] = p1.y;
        }
#pragma unroll
        for (int ii = 0; ii < 4; ii++) {
            int i = qy * 4 + ii;
#pragma unroll
            for (int jj = 0; jj < 4; jj++) {
                float s = sv[ii][jj] * SCALE_QK;
                if (diag && (kx * 4 + jj) > i) s = -1e30f;
                sv[ii][jj] = s;
            }
            float mx = fmaxf(fmaxf(sv[ii][0], sv[ii][1]), fmaxf(sv[ii][2], sv[ii][3]));
#pragma unroll
            for (int off = 8; off > 0; off >>= 1)
                mx = fmaxf(mx, __shfl_xor_sync(0xffffffffu, mx, off));
            float mn = fmaxf(m_[ii], mx);
            float al = __expf(m_[ii] - mn);
            m_[ii] = mn;
            float rs = 0.0f;
#pragma unroll
            for (int jj = 0; jj < 4; jj++) {
                float p = __expf(sv[ii][jj] - mn);
                sv[ii][jj] = p;
                rs += p;
            }
#pragma unroll
            for (int off = 8; off > 0; off >>= 1)
                rs += __shfl_xor_sync(0xffffffffu, rs, off);
            l_[ii] = l_[ii] * al + rs;
#pragma unroll
            for (int jj = 0; jj < 4; jj++)
                *(float2*)&Pd[(kx * 4 + jj) * 130 + 2 * i] =
                    make_float2(sv[ii][jj], sv[ii][jj]);
            if (kx == 0) sAl[i] = al;
        }
        __syncthreads();

#pragma unroll
        for (int ii = 0; ii < 4; ii++) {
            float a = sAl[iy * 4 + ii];
            ull av = pack2(a, a);
#pragma unroll
            for (int p = 0; p < 4; p++) MUL2(o2[ii][p], o2[ii][p], av);
        }
#pragma unroll 2
        for (int j = 0; j < 64; ++j) {
            const ull* pp = (const ull*)&Pd[j * 130 + 8 * iy];
            ull p0 = pp[0], p1 = pp[1], p2 = pp[2], p3 = pp[3];
            ulonglong2 v0 = *(const ulonglong2*)&Vs[j * 128 + 4 * dvx];
            ulonglong2 v1 = *(const ulonglong2*)&Vs[j * 128 + 64 + 4 * dvx];
            FMA2(o2[0][0], p0, v0.x); FMA2(o2[0][1], p0, v0.y);
            FMA2(o2[0][2], p0, v1.x); FMA2(o2[0][3], p0, v1.y);
            FMA2(o2[1][0], p1, v0.x); FMA2(o2[1][1], p1, v0.y);
            FMA2(o2[1][2], p1, v1.x); FMA2(o2[1][3], p1, v1.y);
            FMA2(o2[2][0], p2, v0.x); FMA2(o2[2][1], p2, v0.y);
            FMA2(o2[2][2], p2, v1.x); FMA2(o2[2][3], p2, v1.y);
            FMA2(o2[3][0], p3, v0.x); FMA2(o2[3][1], p3, v0.y);
            FMA2(o2[3][2], p3, v1.x); FMA2(o2[3][3], p3, v1.y);
        }
    }

    if (kx == 0) {
#pragma unroll
        for (int ii = 0; ii < 4; ii++) sL[qy * 4 + ii] = l_[ii];
    }
    __syncthreads();
    const int b = bh >> 4, h = bh & 15;
    float* Og = g_attn + (size_t)(b * 2048 + qt * 64) * 2048 + h * 128;
#pragma unroll
    for (int ii = 0; ii < 4; ii++) {
        int i = iy * 4 + ii;
        float inv = 1.0f / sL[i];
#pragma unroll
        for (int g = 0; g < 2; g++) {
            float2 p0 = unpack2(o2[ii][2 * g]);
            float2 p1 = unpack2(o2[ii][2 * g + 1]);
            *(float4*)&Og[(size_t)i * 2048 + g * 64 + 4 * dvx] =
                make_float4(p0.x * inv, p0.y * inv, p1.x * inv, p1.y * inv);
        }
    }
}

// ---------------- launch -------------------------------------------------
extern "C" void kernel_launch(void* const* d_in, const int* in_sizes, int n_in,
                              void* d_out, int out_size) {
    const float* x  = (const float*)d_in[0];
    const float* wq = (const float*)d_in[1];
    const float* wk = (const float*)d_in[2];
    const float* wv = (const float*)d_in[3];
    const float* wo = (const float*)d_in[4];
    float* out = (float*)d_out;

    cudaFuncSetAttribute(attn_kernel, cudaFuncAttributeMaxDynamicSharedMemorySize,
                         ATTN_SMEM_BYTES);

    rope_tab_kernel<<<512, 256>>>();
    gemm_mma<1><<<dim3(48, 32), 256>>>(x, wq, wk, wv, nullptr);
    attn_kernel<<<dim3(32, 32), 256, ATTN_SMEM_BYTES>>>();
    gemm_mma<0><<<dim3(16, 32), 256>>>(nullptr, wo, nullptr, nullptr, out);
}

// round 10
// speedup vs baseline: 3.6028x; 1.5213x over previous
#include <cuda_runtime.h>
#include <cuda_bf16.h>
#include <math.h>
#include <stdint.h>

// Problem: B=2, S=2048, D=2048, H=16, hd=128
#define SCALE_QK 0.08838834764831843f  // 1/sqrt(128)

// ---------------- scratch (device globals: allocation-free) ----------------
// q/k/v stored as split bf16 planes (hi + lo), layout [b][h][s][d]
#define QKV_ELEMS (2 * 16 * 2048 * 128)
__device__ __align__(16) __nv_bfloat16 g_qh[QKV_ELEMS], g_ql[QKV_ELEMS];
__device__ __align__(16) __nv_bfloat16 g_kh[QKV_ELEMS], g_kl[QKV_ELEMS];
__device__ __align__(16) __nv_bfloat16 g_vh[QKV_ELEMS], g_vl[QKV_ELEMS];
__device__ __align__(16) float g_attn[4096 * 2048];   // [b*S + s][h*128 + d]
__device__ __align__(16) float g_tab[2048 * 128];     // [s][0..63]=cos, [64..127]=sin

// ---------------- PTX helpers ---------------------------------------------
__device__ __forceinline__ uint32_t smem_u32(const void* p) {
    uint32_t a;
    asm("{ .reg .u64 t; cvta.to.shared.u64 t, %1; cvt.u32.u64 %0, t; }" : "=r"(a) : "l"(p));
    return a;
}

#define LDSM4(r0, r1, r2, r3, addr) \
    asm volatile("ldmatrix.sync.aligned.m8n8.x4.shared.b16 {%0,%1,%2,%3}, [%4];" \
                 : "=r"(r0), "=r"(r1), "=r"(r2), "=r"(r3) : "r"(addr))
#define LDSM4T(r0, r1, r2, r3, addr) \
    asm volatile("ldmatrix.sync.aligned.m8n8.x4.trans.shared.b16 {%0,%1,%2,%3}, [%4];" \
                 : "=r"(r0), "=r"(r1), "=r"(r2), "=r"(r3) : "r"(addr))

// D(16x8,f32) += A(16x16,bf16) x B(16x8,bf16)
#define MMA(d, a, b0, b1) \
    asm volatile("mma.sync.aligned.m16n8k16.row.col.f32.bf16.bf16.f32 " \
                 "{%0,%1,%2,%3}, {%4,%5,%6,%7}, {%8,%9}, {%0,%1,%2,%3};" \
                 : "+f"((d)[0]), "+f"((d)[1]), "+f"((d)[2]), "+f"((d)[3]) \
                 : "r"((a)[0]), "r"((a)[1]), "r"((a)[2]), "r"((a)[3]), \
                   "r"(b0), "r"(b1))

#define CP16(dst, src) \
    asm volatile("cp.async.cg.shared.global [%0], [%1], 16;" :: "r"(dst), "l"(src) : "memory")
#define CP_COMMIT() asm volatile("cp.async.commit_group;" ::: "memory")
#define CP_WAIT0()  asm volatile("cp.async.wait_group 0;" ::: "memory")
#define CP_WAIT1()  asm volatile("cp.async.wait_group 1;" ::: "memory")

// split a float pair into packed bf16 hi + bf16 lo (2-term decomposition)
__device__ __forceinline__ void split2(float x, float y, uint32_t& hi, uint32_t& lo) {
    __nv_bfloat16 xh = __float2bfloat16_rn(x), yh = __float2bfloat16_rn(y);
    float xr = x - __bfloat162float(xh);
    float yr = y - __bfloat162float(yh);
    __nv_bfloat162 hp; hp.x = xh; hp.y = yh;
    __nv_bfloat162 lp = __floats2bfloat162_rn(xr, yr);
    hi = *(uint32_t*)&hp;
    lo = *(uint32_t*)&lp;
}

// ---------------- RoPE table ----------------------------------------------
__global__ void rope_tab_kernel() {
    int idx = blockIdx.x * 256 + threadIdx.x;
    if (idx >= 2048 * 64) return;
    int s = idx >> 6, f = idx & 63;
    double invf = pow(10000.0, -2.0 * (double)f / 128.0);
    double ang = (double)s * invf;
    g_tab[s * 128 + f]      = (float)cos(ang);
    g_tab[s * 128 + 64 + f] = (float)sin(ang);
}

// ---------------- bf16-split mma.sync GEMM: C = A @ W^T --------------------
// MODE 1: A = x; nt in [0,48): region -> {wq,wk,wv}, head h = nt&15;
//         epilogue applies RoPE (q,k) then SPLITS result into bf16 hi/lo
//         planes in [b][h][s][d] for the mma attention kernel.
// MODE 0: A = g_attn, W = wo, plain fp32 store to out.
#define ASTR 24  // bf16 elems per smem row (16 data + 8 pad) = 48 bytes

template <int MODE>
__global__ __launch_bounds__(256, 1) void gemm_mma(
    const float* __restrict__ Ain, const float* __restrict__ w0,
    const float* __restrict__ w1, const float* __restrict__ w2,
    float* __restrict__ outp)
{
    __shared__ __nv_bfloat16 smb[2][4][128 * ASTR];   // 49152 B

    const int tid = threadIdx.x;
    const int wid = tid >> 5, lane = tid & 31;
    const int wm = wid >> 2, wn = wid & 3;
    const int nt = blockIdx.x, mt = blockIdx.y;

    const float* A = (MODE == 0) ? g_attn : Ain;
    const float* W;
    int region = 0, nloc;
    if (MODE == 0) { W = w0; nloc = nt; }
    else {
        region = nt >> 4;
        W = (region == 0) ? w0 : (region == 1) ? w1 : w2;
        nloc = nt & 15;
    }

    const int prow = tid >> 1, phalf = tid & 1;
    const float* Ap = A + (size_t)(mt * 128 + prow) * 2048 + phalf * 8;
    const float* Bp = W + (size_t)(nloc * 128 + prow) * 2048 + phalf * 8;

    uint32_t aAddr[2][2], bAddr[2][2];
#pragma unroll
    for (int bufi = 0; bufi < 2; bufi++)
#pragma unroll
        for (int p = 0; p < 2; p++) {
            aAddr[bufi][p] = smem_u32(&smb[bufi][p][0]) +
                (uint32_t)((wm * 64 + (lane & 15)) * 48 + ((lane >> 4) & 1) * 16);
            bAddr[bufi][p] = smem_u32(&smb[bufi][2 + p][0]) +
                (uint32_t)((wn * 32 + ((lane >> 4) & 1) * 8 + (lane & 7)) * 48 +
                           ((lane >> 3) & 1) * 16);
        }

    float acc[4][4][4];
#pragma unroll
    for (int m = 0; m < 4; m++)
#pragma unroll
        for (int n = 0; n < 4; n++)
#pragma unroll
            for (int e = 0; e < 4; e++) acc[m][n][e] = 0.0f;

    float4 ra0, ra1, rb0, rb1;
    ra0 = *(const float4*)(Ap + 0);
    ra1 = *(const float4*)(Ap + 4);
    rb0 = *(const float4*)(Bp + 0);
    rb1 = *(const float4*)(Bp + 4);

#define STORE_STAGE(bufi)                                                       \
    do {                                                                        \
        uint4 h, l;                                                             \
        split2(ra0.x, ra0.y, h.x, l.x); split2(ra0.z, ra0.w, h.y, l.y);         \
        split2(ra1.x, ra1.y, h.z, l.z); split2(ra1.z, ra1.w, h.w, l.w);         \
        *(uint4*)&smb[bufi][0][prow * ASTR + phalf * 8] = h;                    \
        *(uint4*)&smb[bufi][1][prow * ASTR + phalf * 8] = l;                    \
        split2(rb0.x, rb0.y, h.x, l.x); split2(rb0.z, rb0.w, h.y, l.y);         \
        split2(rb1.x, rb1.y, h.z, l.z); split2(rb1.z, rb1.w, h.w, l.w);         \
        *(uint4*)&smb[bufi][2][prow * ASTR + phalf * 8] = h;                    \
        *(uint4*)&smb[bufi][3][prow * ASTR + phalf * 8] = l;                    \
    } while (0)

    STORE_STAGE(0);
    __syncthreads();

    for (int s = 0; s < 128; ++s) {
        const int buf = s & 1;
        if (s < 127) {
            ra0 = *(const float4*)(Ap + (s + 1) * 16);
            ra1 = *(const float4*)(Ap + (s + 1) * 16 + 4);
            rb0 = *(const float4*)(Bp + (s + 1) * 16);
            rb1 = *(const float4*)(Bp + (s + 1) * 16 + 4);
        }

        uint32_t af[2][4][4];
        uint32_t bfr[2][4][2];
#pragma unroll
        for (int p = 0; p < 2; p++) {
#pragma unroll
            for (int m = 0; m < 4; m++)
                LDSM4(af[p][m][0], af[p][m][1], af[p][m][2], af[p][m][3],
                      aAddr[buf][p] + (uint32_t)(m * 16 * 48));
#pragma unroll
            for (int g = 0; g < 2; g++) {
                uint32_t r0, r1, r2, r3;
                LDSM4(r0, r1, r2, r3, bAddr[buf][p] + (uint32_t)(g * 16 * 48));
                bfr[p][2 * g][0] = r0; bfr[p][2 * g][1] = r1;
                bfr[p][2 * g + 1][0] = r2; bfr[p][2 * g + 1][1] = r3;
            }
        }

#pragma unroll
        for (int m = 0; m < 4; m++)
#pragma unroll
            for (int n = 0; n < 4; n++) {
                MMA(acc[m][n], af[0][m], bfr[0][n][0], bfr[0][n][1]);  // hi*hi
                MMA(acc[m][n], af[0][m], bfr[1][n][0], bfr[1][n][1]);  // hi*lo
                MMA(acc[m][n], af[1][m], bfr[0][n][0], bfr[0][n][1]);  // lo*hi
            }

        if (s < 127) STORE_STAGE(buf ^ 1);
        __syncthreads();
    }
#undef STORE_STAGE

    // ---- epilogue ----
    const int qr = lane >> 2, qc = 2 * (lane & 3);
#pragma unroll
    for (int m = 0; m < 4; m++) {
        const int r0 = mt * 128 + wm * 64 + m * 16 + qr;
#pragma unroll
        for (int half = 0; half < 2; half++) {
            const int r = r0 + half * 8;
            if (MODE == 0) {
                float* drow = outp + (size_t)r * 2048 + nt * 128;
#pragma unroll
                for (int n = 0; n < 4; n++) {
                    const int col = wn * 32 + n * 8 + qc;
                    *(float2*)&drow[col] =
                        make_float2(acc[m][n][2 * half], acc[m][n][2 * half + 1]);
                }
            } else {
                const int b = r >> 11, spos = r & 2047, h = nt & 15;
                __nv_bfloat16* dh = (region == 0) ? g_qh : (region == 1) ? g_kh : g_vh;
                __nv_bfloat16* dl = (region == 0) ? g_ql : (region == 1) ? g_kl : g_vl;
                const size_t rowb = ((size_t)(b * 16 + h) * 2048 + spos) * 128;
                const float* tab = g_tab + spos * 128;
#pragma unroll
                for (int n = 0; n < 4; n++) {
                    const int col = wn * 32 + n * 8 + qc;
                    float v0 = acc[m][n][2 * half], v1 = acc[m][n][2 * half + 1];
                    float2 ov;
                    if (region < 2) {  // RoPE rotate pair (2f, 2f+1)
                        const int f = col >> 1;
                        float c = tab[f], sn = tab[64 + f];
                        ov = make_float2(v0 * c - v1 * sn, v0 * sn + v1 * c);
                    } else {
                        ov = make_float2(v0, v1);
                    }
                    uint32_t hh, ll;
                    split2(ov.x, ov.y, hh, ll);
                    *(uint32_t*)&dh[rowb + col] = hh;
                    *(uint32_t*)&dl[rowb + col] = ll;
                }
            }
        }
    }
}

// ---------------- Flash attention: split-bf16 mma.sync --------------------
// CTA: 128 q-rows x 64-kv tiles, 8 warps x 16 q-rows. Causal, heavy-first.
// Smem (bf16, stride 136 rows -> conflict-free LDSM):
//   Qh[128x136] Ql[128x136] | 2 bufs x {Kh,Kl,Vh,Vl}[64x136]
// cp.async double-buffered K/V pipeline.
#define AQS  17408            // 128*136 elems, one Q plane
#define AKVS 8704             // 64*136 elems, one K/V plane
#define ATT_SMEM_BYTES ((2 * AQS + 2 * 4 * AKVS) * 2)

__device__ __forceinline__ void ldkv(uint32_t sb, int buf, size_t kvoff, int tid) {
#pragma unroll
    for (int t = 0; t < 16; t++) {
        const int plane = t >> 2;
        int rem = (t & 3) * 256 + tid;
        int row = rem >> 4, ch = rem & 15;
        uint32_t dst = sb +
            (uint32_t)((2 * AQS + buf * 4 * AKVS + plane * AKVS + row * 136 + ch * 8) * 2);
        const __nv_bfloat16* src =
            ((plane == 0) ? g_kh : (plane == 1) ? g_kl : (plane == 2) ? g_vh : g_vl)
            + kvoff + row * 128 + ch * 8;
        CP16(dst, src);
    }
}

__global__ __launch_bounds__(256, 1) void attn_mma() {
    extern __shared__ __nv_bfloat16 smb[];
    const uint32_t sb = smem_u32(smb);
    const int tid = threadIdx.x;
    const int lane = tid & 31, w = tid >> 5;
    const int t4 = lane & 3, r = lane >> 2;
    const int bh = blockIdx.x;
    const int qt = 15 - blockIdx.y;            // heavy diagonals first
    const int kvmax = 2 * qt + 2;
    const size_t bh_off = (size_t)bh * 2048 * 128;
    const size_t qoff = bh_off + (size_t)qt * 128 * 128;

    // ---- group 0: Q (both planes) + KV tile 0 ----
#pragma unroll
    for (int t = 0; t < 16; t++) {
        const int plane = t >> 3;
        int rem = (t & 7) * 256 + tid;
        int row = rem >> 4, ch = rem & 15;
        uint32_t dst = sb + (uint32_t)((plane * AQS + row * 136 + ch * 8) * 2);
        const __nv_bfloat16* src = (plane ? g_ql : g_qh) + qoff + row * 128 + ch * 8;
        CP16(dst, src);
    }
    ldkv(sb, 0, bh_off, tid);
    CP_COMMIT();

    float o[16][4];
#pragma unroll
    for (int n = 0; n < 16; n++)
#pragma unroll
        for (int e = 0; e < 4; e++) o[n][e] = 0.0f;
    float m0 = -INFINITY, m1 = -INFINITY, l0 = 0.0f, l1 = 0.0f;

    // ldmatrix lane addresses (bytes)
    uint32_t qaddr[2];
#pragma unroll
    for (int p = 0; p < 2; p++)
        qaddr[p] = sb + (uint32_t)((p * AQS + (w * 16 + (lane & 15)) * 136 +
                                    (lane >> 4) * 8) * 2);
    const uint32_t krow = (uint32_t)(((8 * (lane >> 4) + (lane & 7)) * 136 +
                                      ((lane >> 3) & 1) * 8) * 2);
    const uint32_t vrow = (uint32_t)((((lane & 7) + 8 * ((lane >> 3) & 1)) * 136 +
                                      (lane >> 4) * 8) * 2);
    const int i0 = qt * 128 + w * 16 + r;
    const int i1 = i0 + 8;

    for (int kv = 0; kv < kvmax; ++kv) {
        const int buf = kv & 1;
        if (kv + 1 < kvmax) {
            ldkv(sb, buf ^ 1, bh_off + (size_t)(kv + 1) * 64 * 128, tid);
            CP_COMMIT();
            CP_WAIT1();
        } else {
            CP_WAIT0();
        }
        __syncthreads();

        const uint32_t kb0 = sb + (uint32_t)((2 * AQS + buf * 4 * AKVS) * 2) + krow;
        const uint32_t kb1 = kb0 + (uint32_t)(AKVS * 2);
        const uint32_t vb0 = sb + (uint32_t)((2 * AQS + buf * 4 * AKVS + 2 * AKVS) * 2) + vrow;
        const uint32_t vb1 = vb0 + (uint32_t)(AKVS * 2);

        // ---- QK^T: 3-product split bf16 ----
        float sc[8][4];
#pragma unroll
        for (int n = 0; n < 8; n++)
#pragma unroll
            for (int e = 0; e < 4; e++) sc[n][e] = 0.0f;

#pragma unroll
        for (int ks = 0; ks < 8; ++ks) {
            uint32_t ah[4], al[4];
            LDSM4(ah[0], ah[1], ah[2], ah[3], qaddr[0] + ks * 32);
            LDSM4(al[0], al[1], al[2], al[3], qaddr[1] + ks * 32);
#pragma unroll
            for (int jg = 0; jg < 4; ++jg) {
                uint32_t kh[4], kl[4];
                const uint32_t off = (uint32_t)(jg * 4352 + ks * 32);
                LDSM4(kh[0], kh[1], kh[2], kh[3], kb0 + off);
                LDSM4(kl[0], kl[1], kl[2], kl[3], kb1 + off);
                MMA(sc[2 * jg], ah, kh[0], kh[1]);
                MMA(sc[2 * jg], ah, kl[0], kl[1]);
                MMA(sc[2 * jg], al, kh[0], kh[1]);
                MMA(sc[2 * jg + 1], ah, kh[2], kh[3]);
                MMA(sc[2 * jg + 1], ah, kl[2], kl[3]);
                MMA(sc[2 * jg + 1], al, kh[2], kh[3]);
            }
        }

        // ---- online softmax (rows r, r+8 per thread; quad reductions) ----
        const bool needmask = (kv * 64 + 63) > (qt * 128 + w * 16);
        float mx0 = -INFINITY, mx1 = -INFINITY;
#pragma unroll
        for (int n = 0; n < 8; n++) {
#pragma unroll
            for (int e = 0; e < 4; e++) {
                float s = sc[n][e] * SCALE_QK;
                if (needmask) {
                    int jc = kv * 64 + n * 8 + 2 * t4 + (e & 1);
                    int ir = (e < 2) ? i0 : i1;
                    if (jc > ir) s = -1e30f;
                }
                sc[n][e] = s;
            }
            mx0 = fmaxf(mx0, fmaxf(sc[n][0], sc[n][1]));
            mx1 = fmaxf(mx1, fmaxf(sc[n][2], sc[n][3]));
        }
        mx0 = fmaxf(mx0, __shfl_xor_sync(0xffffffffu, mx0, 1));
        mx0 = fmaxf(mx0, __shfl_xor_sync(0xffffffffu, mx0, 2));
        mx1 = fmaxf(mx1, __shfl_xor_sync(0xffffffffu, mx1, 1));
        mx1 = fmaxf(mx1, __shfl_xor_sync(0xffffffffu, mx1, 2));

        const float mn0 = fmaxf(m0, mx0), mn1 = fmaxf(m1, mx1);
        const float a0 = __expf(m0 - mn0), a1 = __expf(m1 - mn1);
        m0 = mn0; m1 = mn1;
        float rs0 = 0.0f, rs1 = 0.0f;
#pragma unroll
        for (int n = 0; n < 8; n++) {
            float p0 = __expf(sc[n][0] - mn0), p1 = __expf(sc[n][1] - mn0);
            float p2 = __expf(sc[n][2] - mn1), p3 = __expf(sc[n][3] - mn1);
            sc[n][0] = p0; sc[n][1] = p1; sc[n][2] = p2; sc[n][3] = p3;
            rs0 += p0 + p1; rs1 += p2 + p3;
        }
        rs0 += __shfl_xor_sync(0xffffffffu, rs0, 1);
        rs0 += __shfl_xor_sync(0xffffffffu, rs0, 2);
        rs1 += __shfl_xor_sync(0xffffffffu, rs1, 1);
        rs1 += __shfl_xor_sync(0xffffffffu, rs1, 2);
        l0 = l0 * a0 + rs0;
        l1 = l1 * a1 + rs1;

#pragma unroll
        for (int n = 0; n < 16; n++) {
            o[n][0] *= a0; o[n][1] *= a0;
            o[n][2] *= a1; o[n][3] *= a1;
        }

        // pack P -> bf16 hi/lo A-fragments (c-layout == A-layout identity)
        uint32_t ph0[8], pl0[8], ph1[8], pl1[8];
#pragma unroll
        for (int n = 0; n < 8; n++) {
            split2(sc[n][0], sc[n][1], ph0[n], pl0[n]);
            split2(sc[n][2], sc[n][3], ph1[n], pl1[n]);
        }

        // ---- P @ V: 3-product split bf16 ----
#pragma unroll
        for (int ks = 0; ks < 4; ++ks) {
            uint32_t aPh[4] = {ph0[2 * ks], ph1[2 * ks], ph0[2 * ks + 1], ph1[2 * ks + 1]};
            uint32_t aPl[4] = {pl0[2 * ks], pl1[2 * ks], pl0[2 * ks + 1], pl1[2 * ks + 1]};
#pragma unroll
            for (int ng = 0; ng < 8; ++ng) {
                uint32_t vh[4], vl[4];
                const uint32_t off = (uint32_t)(ks * 4352 + ng * 32);
                LDSM4T(vh[0], vh[1], vh[2], vh[3], vb0 + off);
                LDSM4T(vl[0], vl[1], vl[2], vl[3], vb1 + off);
                MMA(o[2 * ng], aPh, vh[0], vh[1]);
                MMA(o[2 * ng], aPh, vl[0], vl[1]);
                MMA(o[2 * ng], aPl, vh[0], vh[1]);
                MMA(o[2 * ng + 1], aPh, vh[2], vh[3]);
                MMA(o[2 * ng + 1], aPh, vl[2], vl[3]);
                MMA(o[2 * ng + 1], aPl, vh[2], vh[3]);
            }
        }
        __syncthreads();   // all warps done with buf before it is overwritten
    }

    // ---- finalize: divide by l, write g_attn [b*S+s][h*128+dv] ----
    const float inv0 = 1.0f / l0, inv1 = 1.0f / l1;
    const int b = bh >> 4, h = bh & 15;
    float* O0 = g_attn + (size_t)(b * 2048 + i0) * 2048 + h * 128;
    float* O1 = O0 + (size_t)8 * 2048;
#pragma unroll
    for (int n = 0; n < 16; n++) {
        const int c = n * 8 + 2 * t4;
        *(float2*)&O0[c] = make_float2(o[n][0] * inv0, o[n][1] * inv0);
        *(float2*)&O1[c] = make_float2(o[n][2] * inv1, o[n][3] * inv1);
    }
}

// ---------------- launch -------------------------------------------------
extern "C" void kernel_launch(void* const* d_in, const int* in_sizes, int n_in,
                              void* d_out, int out_size) {
    const float* x  = (const float*)d_in[0];
    const float* wq = (const float*)d_in[1];
    const float* wk = (const float*)d_in[2];
    const float* wv = (const float*)d_in[3];
    const float* wo = (const float*)d_in[4];
    float* out = (float*)d_out;

    cudaFuncSetAttribute(attn_mma, cudaFuncAttributeMaxDynamicSharedMemorySize,
                         ATT_SMEM_BYTES);

    rope_tab_kernel<<<512, 256>>>();
    gemm_mma<1><<<dim3(48, 32), 256>>>(x, wq, wk, wv, nullptr);
    attn_mma<<<dim3(32, 16), 256, ATT_SMEM_BYTES>>>();
    gemm_mma<0><<<dim3(16, 32), 256>>>(nullptr, wo, nullptr, nullptr, out);
}

// round 15
// speedup vs baseline: 4.6769x; 1.2981x over previous
#include <cuda_runtime.h>
#include <cuda_bf16.h>
#include <math.h>
#include <stdint.h>

// Problem: B=2, S=2048, D=2048, H=16, hd=128
#define SCALE_QK 0.08838834764831843f  // 1/sqrt(128)

// ---------------- scratch (device globals: allocation-free) ----------------
// everything the tensor cores touch lives as split bf16 planes (hi + lo)
#define QKV_ELEMS (2 * 16 * 2048 * 128)
__device__ __align__(16) __nv_bfloat16 g_qh[QKV_ELEMS], g_ql[QKV_ELEMS];
__device__ __align__(16) __nv_bfloat16 g_kh[QKV_ELEMS], g_kl[QKV_ELEMS];
__device__ __align__(16) __nv_bfloat16 g_vh[QKV_ELEMS], g_vl[QKV_ELEMS];
__device__ __align__(16) __nv_bfloat16 g_xh[4096 * 2048], g_xl[4096 * 2048];
__device__ __align__(16) __nv_bfloat16 g_ah[4096 * 2048], g_al[4096 * 2048];  // attn out
__device__ __align__(16) __nv_bfloat16 g_wqh[2048 * 2048], g_wql[2048 * 2048];
__device__ __align__(16) __nv_bfloat16 g_wkh[2048 * 2048], g_wkl[2048 * 2048];
__device__ __align__(16) __nv_bfloat16 g_wvh[2048 * 2048], g_wvl[2048 * 2048];
__device__ __align__(16) __nv_bfloat16 g_woh[2048 * 2048], g_wol[2048 * 2048];
__device__ __align__(16) float g_tab[2048 * 128];     // [s][0..63]=cos, [64..127]=sin

// ---------------- PTX helpers ---------------------------------------------
__device__ __forceinline__ uint32_t smem_u32(const void* p) {
    uint32_t a;
    asm("{ .reg .u64 t; cvta.to.shared.u64 t, %1; cvt.u32.u64 %0, t; }" : "=r"(a) : "l"(p));
    return a;
}

#define LDSM4(r0, r1, r2, r3, addr) \
    asm volatile("ldmatrix.sync.aligned.m8n8.x4.shared.b16 {%0,%1,%2,%3}, [%4];" \
                 : "=r"(r0), "=r"(r1), "=r"(r2), "=r"(r3) : "r"(addr))
#define LDSM4T(r0, r1, r2, r3, addr) \
    asm volatile("ldmatrix.sync.aligned.m8n8.x4.trans.shared.b16 {%0,%1,%2,%3}, [%4];" \
                 : "=r"(r0), "=r"(r1), "=r"(r2), "=r"(r3) : "r"(addr))

// D(16x8,f32) += A(16x16,bf16) x B(16x8,bf16)
#define MMA(d, a, b0, b1) \
    asm volatile("mma.sync.aligned.m16n8k16.row.col.f32.bf16.bf16.f32 " \
                 "{%0,%1,%2,%3}, {%4,%5,%6,%7}, {%8,%9}, {%0,%1,%2,%3};" \
                 : "+f"((d)[0]), "+f"((d)[1]), "+f"((d)[2]), "+f"((d)[3]) \
                 : "r"((a)[0]), "r"((a)[1]), "r"((a)[2]), "r"((a)[3]), \
                   "r"(b0), "r"(b1))

#define CP16(dst, src) \
    asm volatile("cp.async.cg.shared.global [%0], [%1], 16;" :: "r"(dst), "l"(src) : "memory")
#define CP_COMMIT() asm volatile("cp.async.commit_group;" ::: "memory")
#define CP_WAIT0()  asm volatile("cp.async.wait_group 0;" ::: "memory")
#define CP_WAIT1()  asm volatile("cp.async.wait_group 1;" ::: "memory")

// split a float pair into packed bf16 hi + bf16 lo (2-term decomposition)
__device__ __forceinline__ void split2(float x, float y, uint32_t& hi, uint32_t& lo) {
    __nv_bfloat16 xh = __float2bfloat16_rn(x), yh = __float2bfloat16_rn(y);
    float xr = x - __bfloat162float(xh);
    float yr = y - __bfloat162float(yh);
    __nv_bfloat162 hp; hp.x = xh; hp.y = yh;
    __nv_bfloat162 lp = __floats2bfloat162_rn(xr, yr);
    hi = *(uint32_t*)&hp;
    lo = *(uint32_t*)&lp;
}

// ---------------- RoPE table ----------------------------------------------
__global__ void rope_tab_kernel() {
    int idx = blockIdx.x * 256 + threadIdx.x;
    if (idx >= 2048 * 64) return;
    int s = idx >> 6, f = idx & 63;
    double invf = pow(10000.0, -2.0 * (double)f / 128.0);
    double ang = (double)s * invf;
    g_tab[s * 128 + f]      = (float)cos(ang);
    g_tab[s * 128 + 64 + f] = (float)sin(ang);
}

// ---------------- fp32 -> split bf16 plane conversion ----------------------
// Destination selected in DEVICE code (passing __device__ symbols as kernel
// args from host is UB and was the R11-R14 failure).
template <int SEL>
__global__ void split_planes(const float* __restrict__ src, int n4) {
    int i = blockIdx.x * 256 + threadIdx.x;
    if (i >= n4) return;
    __nv_bfloat16* dh;
    __nv_bfloat16* dl;
    if      (SEL == 0) { dh = g_xh;  dl = g_xl;  }
    else if (SEL == 1) { dh = g_wqh; dl = g_wql; }
    else if (SEL == 2) { dh = g_wkh; dl = g_wkl; }
    else if (SEL == 3) { dh = g_wvh; dl = g_wvl; }
    else               { dh = g_woh; dl = g_wol; }
    float4 v = ((const float4*)src)[i];
    uint32_t h0, l0, h1, l1;
    split2(v.x, v.y, h0, l0);
    split2(v.z, v.w, h1, l1);
    ((uint2*)dh)[i] = make_uint2(h0, h1);
    ((uint2*)dl)[i] = make_uint2(l0, l1);
}

// ---------------- split-bf16 mma.sync GEMM: C = A @ W^T --------------------
// R10-proven structure: tile 128x128, BK=16, 128 stages, double-buffered
// static smem, 8 warps (2x4), 64x32/warp, 3 HMMA products. Operands are
// PRE-SPLIT bf16 planes bound in device code. 2 CTAs/SM.
// MODE 1: A = x planes; nt in [0,48): region -> {wq,wk,wv} planes; RoPE
//         epilogue, writes split planes g_q*/g_k*/g_v* in [b][h][s][d].
// MODE 0: A = attn planes, W = wo planes, fp32 store to out.
#define ASTR 24  // bf16 elems per smem row (16 data + 8 pad) = 48 bytes

template <int MODE>
__global__ __launch_bounds__(256, 2) void gemm_mma(float* __restrict__ outp)
{
    __shared__ __nv_bfloat16 smb[2][4][128 * ASTR];   // 49152 B

    const int tid = threadIdx.x;
    const int wid = tid >> 5, lane = tid & 31;
    const int wm = wid >> 2, wn = wid & 3;
    const int nt = blockIdx.x, mt = blockIdx.y;

    int region = 0, nloc;
    const __nv_bfloat16 *Ah, *Al, *Wh, *Wl;
    if (MODE == 0) {
        Ah = g_ah; Al = g_al; Wh = g_woh; Wl = g_wol; nloc = nt;
    } else {
        Ah = g_xh; Al = g_xl;
        region = nt >> 4;
        Wh = (region == 0) ? g_wqh : (region == 1) ? g_wkh : g_wvh;
        Wl = (region == 0) ? g_wql : (region == 1) ? g_wkl : g_wvl;
        nloc = nt & 15;
    }

    // producer mapping identical to R10: 2 threads per row, 8 elems each
    const int prow = tid >> 1, phalf = tid & 1;
    const __nv_bfloat16* pAh = Ah + (size_t)(mt * 128 + prow) * 2048 + phalf * 8;
    const __nv_bfloat16* pAl = Al + (size_t)(mt * 128 + prow) * 2048 + phalf * 8;
    const __nv_bfloat16* pWh = Wh + (size_t)(nloc * 128 + prow) * 2048 + phalf * 8;
    const __nv_bfloat16* pWl = Wl + (size_t)(nloc * 128 + prow) * 2048 + phalf * 8;

    // ldmatrix lane addresses (byte-identical to R10)
    uint32_t aAddr[2][2], bAddr[2][2];
#pragma unroll
    for (int bufi = 0; bufi < 2; bufi++)
#pragma unroll
        for (int p = 0; p < 2; p++) {
            aAddr[bufi][p] = smem_u32(&smb[bufi][p][0]) +
                (uint32_t)((wm * 64 + (lane & 15)) * 48 + ((lane >> 4) & 1) * 16);
            bAddr[bufi][p] = smem_u32(&smb[bufi][2 + p][0]) +
                (uint32_t)((wn * 32 + ((lane >> 4) & 1) * 8 + (lane & 7)) * 48 +
                           ((lane >> 3) & 1) * 16);
        }

    float acc[4][4][4];
#pragma unroll
    for (int m = 0; m < 4; m++)
#pragma unroll
        for (int n = 0; n < 4; n++)
#pragma unroll
            for (int e = 0; e < 4; e++) acc[m][n][e] = 0.0f;

    uint4 ra_h, ra_l, rb_h, rb_l;
    ra_h = *(const uint4*)(pAh);
    ra_l = *(const uint4*)(pAl);
    rb_h = *(const uint4*)(pWh);
    rb_l = *(const uint4*)(pWl);

#define STORE_STAGE(bufi)                                                       \
    do {                                                                        \
        *(uint4*)&smb[bufi][0][prow * ASTR + phalf * 8] = ra_h;                 \
        *(uint4*)&smb[bufi][1][prow * ASTR + phalf * 8] = ra_l;                 \
        *(uint4*)&smb[bufi][2][prow * ASTR + phalf * 8] = rb_h;                 \
        *(uint4*)&smb[bufi][3][prow * ASTR + phalf * 8] = rb_l;                 \
    } while (0)

    STORE_STAGE(0);
    __syncthreads();

    for (int s = 0; s < 128; ++s) {
        const int buf = s & 1;
        if (s < 127) {  // prefetch next stage (LDG latency hidden by mma below)
            ra_h = *(const uint4*)(pAh + (s + 1) * 16);
            ra_l = *(const uint4*)(pAl + (s + 1) * 16);
            rb_h = *(const uint4*)(pWh + (s + 1) * 16);
            rb_l = *(const uint4*)(pWl + (s + 1) * 16);
        }

        uint32_t af[2][4][4];
        uint32_t bfr[2][4][2];
#pragma unroll
        for (int p = 0; p < 2; p++) {
#pragma unroll
            for (int m = 0; m < 4; m++)
                LDSM4(af[p][m][0], af[p][m][1], af[p][m][2], af[p][m][3],
                      aAddr[buf][p] + (uint32_t)(m * 16 * 48));
#pragma unroll
            for (int g = 0; g < 2; g++) {
                uint32_t r0, r1, r2, r3;
                LDSM4(r0, r1, r2, r3, bAddr[buf][p] + (uint32_t)(g * 16 * 48));
                bfr[p][2 * g][0] = r0; bfr[p][2 * g][1] = r1;
                bfr[p][2 * g + 1][0] = r2; bfr[p][2 * g + 1][1] = r3;
            }
        }

#pragma unroll
        for (int m = 0; m < 4; m++)
#pragma unroll
            for (int n = 0; n < 4; n++) {
                MMA(acc[m][n], af[0][m], bfr[0][n][0], bfr[0][n][1]);  // hi*hi
                MMA(acc[m][n], af[0][m], bfr[1][n][0], bfr[1][n][1]);  // hi*lo
                MMA(acc[m][n], af[1][m], bfr[0][n][0], bfr[0][n][1]);  // lo*hi
            }

        if (s < 127) STORE_STAGE(buf ^ 1);
        __syncthreads();
    }
#undef STORE_STAGE

    // ---- epilogue (identical to R10) ----
    const int qr = lane >> 2, qc = 2 * (lane & 3);
#pragma unroll
    for (int m = 0; m < 4; m++) {
        const int r0 = mt * 128 + wm * 64 + m * 16 + qr;
#pragma unroll
        for (int half = 0; half < 2; half++) {
            const int r = r0 + half * 8;
            if (MODE == 0) {
                float* drow = outp + (size_t)r * 2048 + nt * 128;
#pragma unroll
                for (int n = 0; n < 4; n++) {
                    const int col = wn * 32 + n * 8 + qc;
                    *(float2*)&drow[col] =
                        make_float2(acc[m][n][2 * half], acc[m][n][2 * half + 1]);
                }
            } else {
                const int b = r >> 11, spos = r & 2047, h = nt & 15;
                __nv_bfloat16* dh = (region == 0) ? g_qh : (region == 1) ? g_kh : g_vh;
                __nv_bfloat16* dl = (region == 0) ? g_ql : (region == 1) ? g_kl : g_vl;
                const size_t rowb = ((size_t)(b * 16 + h) * 2048 + spos) * 128;
                const float* tab = g_tab + spos * 128;
#pragma unroll
                for (int n = 0; n < 4; n++) {
                    const int col = wn * 32 + n * 8 + qc;
                    float v0 = acc[m][n][2 * half], v1 = acc[m][n][2 * half + 1];
                    float2 ov;
                    if (region < 2) {  // RoPE rotate pair (2f, 2f+1)
                        const int f = col >> 1;
                        float c = tab[f], sn = tab[64 + f];
                        ov = make_float2(v0 * c - v1 * sn, v0 * sn + v1 * c);
                    } else {
                        ov = make_float2(v0, v1);
                    }
                    uint32_t hh, ll;
                    split2(ov.x, ov.y, hh, ll);
                    *(uint32_t*)&dh[rowb + col] = hh;
                    *(uint32_t*)&dl[rowb + col] = ll;
                }
            }
        }
    }
}

// ---------------- Flash attention: split-bf16 mma.sync (R10-proven) -------
// CTA: 128 q-rows x 64-kv tiles, 8 warps x 16 q-rows. Causal, heavy-first.
#define AQS  17408            // 128*136 elems, one Q plane
#define AKVS 8704             // 64*136 elems, one K/V plane
#define ATT_SMEM_BYTES ((2 * AQS + 2 * 4 * AKVS) * 2)

__device__ __forceinline__ void ldkv(uint32_t sb, int buf, size_t kvoff, int tid) {
#pragma unroll
    for (int t = 0; t < 16; t++) {
        const int plane = t >> 2;
        int rem = (t & 3) * 256 + tid;
        int row = rem >> 4, ch = rem & 15;
        uint32_t dst = sb +
            (uint32_t)((2 * AQS + buf * 4 * AKVS + plane * AKVS + row * 136 + ch * 8) * 2);
        const __nv_bfloat16* src =
            ((plane == 0) ? g_kh : (plane == 1) ? g_kl : (plane == 2) ? g_vh : g_vl)
            + kvoff + row * 128 + ch * 8;
        CP16(dst, src);
    }
}

__global__ __launch_bounds__(256, 1) void attn_mma() {
    extern __shared__ __nv_bfloat16 smb[];
    const uint32_t sb = smem_u32(smb);
    const int tid = threadIdx.x;
    const int lane = tid & 31, w = tid >> 5;
    const int t4 = lane & 3, r = lane >> 2;
    const int bh = blockIdx.x;
    const int qt = 15 - blockIdx.y;            // heavy diagonals first
    const int kvmax = 2 * qt + 2;
    const size_t bh_off = (size_t)bh * 2048 * 128;
    const size_t qoff = bh_off + (size_t)qt * 128 * 128;

#pragma unroll
    for (int t = 0; t < 16; t++) {
        const int plane = t >> 3;
        int rem = (t & 7) * 256 + tid;
        int row = rem >> 4, ch = rem & 15;
        uint32_t dst = sb + (uint32_t)((plane * AQS + row * 136 + ch * 8) * 2);
        const __nv_bfloat16* src = (plane ? g_ql : g_qh) + qoff + row * 128 + ch * 8;
        CP16(dst, src);
    }
    ldkv(sb, 0, bh_off, tid);
    CP_COMMIT();

    float o[16][4];
#pragma unroll
    for (int n = 0; n < 16; n++)
#pragma unroll
        for (int e = 0; e < 4; e++) o[n][e] = 0.0f;
    float m0 = -INFINITY, m1 = -INFINITY, l0 = 0.0f, l1 = 0.0f;

    uint32_t qaddr[2];
#pragma unroll
    for (int p = 0; p < 2; p++)
        qaddr[p] = sb + (uint32_t)((p * AQS + (w * 16 + (lane & 15)) * 136 +
                                    (lane >> 4) * 8) * 2);
    const uint32_t krow = (uint32_t)(((8 * (lane >> 4) + (lane & 7)) * 136 +
                                      ((lane >> 3) & 1) * 8) * 2);
    const uint32_t vrow = (uint32_t)((((lane & 7) + 8 * ((lane >> 3) & 1)) * 136 +
                                      (lane >> 4) * 8) * 2);
    const int i0 = qt * 128 + w * 16 + r;
    const int i1 = i0 + 8;

    for (int kv = 0; kv < kvmax; ++kv) {
        const int buf = kv & 1;
        if (kv + 1 < kvmax) {
            ldkv(sb, buf ^ 1, bh_off + (size_t)(kv + 1) * 64 * 128, tid);
            CP_COMMIT();
            CP_WAIT1();
        } else {
            CP_WAIT0();
        }
        __syncthreads();

        const uint32_t kb0 = sb + (uint32_t)((2 * AQS + buf * 4 * AKVS) * 2) + krow;
        const uint32_t kb1 = kb0 + (uint32_t)(AKVS * 2);
        const uint32_t vb0 = sb + (uint32_t)((2 * AQS + buf * 4 * AKVS + 2 * AKVS) * 2) + vrow;
        const uint32_t vb1 = vb0 + (uint32_t)(AKVS * 2);

        // ---- QK^T: 3-product split bf16 ----
        float sc[8][4];
#pragma unroll
        for (int n = 0; n < 8; n++)
#pragma unroll
            for (int e = 0; e < 4; e++) sc[n][e] = 0.0f;

#pragma unroll
        for (int ks = 0; ks < 8; ++ks) {
            uint32_t ah[4], al[4];
            LDSM4(ah[0], ah[1], ah[2], ah[3], qaddr[0] + ks * 32);
            LDSM4(al[0], al[1], al[2], al[3], qaddr[1] + ks * 32);
#pragma unroll
            for (int jg = 0; jg < 4; ++jg) {
                uint32_t kh[4], kl[4];
                const uint32_t off = (uint32_t)(jg * 4352 + ks * 32);
                LDSM4(kh[0], kh[1], kh[2], kh[3], kb0 + off);
                LDSM4(kl[0], kl[1], kl[2], kl[3], kb1 + off);
                MMA(sc[2 * jg], ah, kh[0], kh[1]);
                MMA(sc[2 * jg], ah, kl[0], kl[1]);
                MMA(sc[2 * jg], al, kh[0], kh[1]);
                MMA(sc[2 * jg + 1], ah, kh[2], kh[3]);
                MMA(sc[2 * jg + 1], ah, kl[2], kl[3]);
                MMA(sc[2 * jg + 1], al, kh[2], kh[3]);
            }
        }

        // ---- online softmax ----
        const bool needmask = (kv * 64 + 63) > (qt * 128 + w * 16);
        float mx0 = -INFINITY, mx1 = -INFINITY;
#pragma unroll
        for (int n = 0; n < 8; n++) {
#pragma unroll
            for (int e = 0; e < 4; e++) {
                float s = sc[n][e] * SCALE_QK;
                if (needmask) {
                    int jc = kv * 64 + n * 8 + 2 * t4 + (e & 1);
                    int ir = (e < 2) ? i0 : i1;
                    if (jc > ir) s = -1e30f;
                }
                sc[n][e] = s;
            }
            mx0 = fmaxf(mx0, fmaxf(sc[n][0], sc[n][1]));
            mx1 = fmaxf(mx1, fmaxf(sc[n][2], sc[n][3]));
        }
        mx0 = fmaxf(mx0, __shfl_xor_sync(0xffffffffu, mx0, 1));
        mx0 = fmaxf(mx0, __shfl_xor_sync(0xffffffffu, mx0, 2));
        mx1 = fmaxf(mx1, __shfl_xor_sync(0xffffffffu, mx1, 1));
        mx1 = fmaxf(mx1, __shfl_xor_sync(0xffffffffu, mx1, 2));

        const float mn0 = fmaxf(m0, mx0), mn1 = fmaxf(m1, mx1);
        const float a0 = __expf(m0 - mn0), a1 = __expf(m1 - mn1);
        m0 = mn0; m1 = mn1;
        float rs0 = 0.0f, rs1 = 0.0f;
#pragma unroll
        for (int n = 0; n < 8; n++) {
            float p0 = __expf(sc[n][0] - mn0), p1 = __expf(sc[n][1] - mn0);
            float p2 = __expf(sc[n][2] - mn1), p3 = __expf(sc[n][3] - mn1);
            sc[n][0] = p0; sc[n][1] = p1; sc[n][2] = p2; sc[n][3] = p3;
            rs0 += p0 + p1; rs1 += p2 + p3;
        }
        rs0 += __shfl_xor_sync(0xffffffffu, rs0, 1);
        rs0 += __shfl_xor_sync(0xffffffffu, rs0, 2);
        rs1 += __shfl_xor_sync(0xffffffffu, rs1, 1);
        rs1 += __shfl_xor_sync(0xffffffffu, rs1, 2);
        l0 = l0 * a0 + rs0;
        l1 = l1 * a1 + rs1;

#pragma unroll
        for (int n = 0; n < 16; n++) {
            o[n][0] *= a0; o[n][1] *= a0;
            o[n][2] *= a1; o[n][3] *= a1;
        }

        // pack P -> bf16 hi/lo A-fragments (c-layout == A-layout identity)
        uint32_t ph0[8], pl0[8], ph1[8], pl1[8];
#pragma unroll
        for (int n = 0; n < 8; n++) {
            split2(sc[n][0], sc[n][1], ph0[n], pl0[n]);
            split2(sc[n][2], sc[n][3], ph1[n], pl1[n]);
        }

        // ---- P @ V: 3-product split bf16 ----
#pragma unroll
        for (int ks = 0; ks < 4; ++ks) {
            uint32_t aPh[4] = {ph0[2 * ks], ph1[2 * ks], ph0[2 * ks + 1], ph1[2 * ks + 1]};
            uint32_t aPl[4] = {pl0[2 * ks], pl1[2 * ks], pl0[2 * ks + 1], pl1[2 * ks + 1]};
#pragma unroll
            for (int ng = 0; ng < 8; ++ng) {
                uint32_t vh[4], vl[4];
                const uint32_t off = (uint32_t)(ks * 4352 + ng * 32);
                LDSM4T(vh[0], vh[1], vh[2], vh[3], vb0 + off);
                LDSM4T(vl[0], vl[1], vl[2], vl[3], vb1 + off);
                MMA(o[2 * ng], aPh, vh[0], vh[1]);
                MMA(o[2 * ng], aPh, vl[0], vl[1]);
                MMA(o[2 * ng], aPl, vh[0], vh[1]);
                MMA(o[2 * ng + 1], aPh, vh[2], vh[3]);
                MMA(o[2 * ng + 1], aPh, vl[2], vl[3]);
                MMA(o[2 * ng + 1], aPl, vh[2], vh[3]);
            }
        }
        __syncthreads();
    }

    // ---- finalize: divide by l, write split planes for the WO GEMM ----
    const float inv0 = 1.0f / l0, inv1 = 1.0f / l1;
    const int b = bh >> 4, h = bh & 15;
    const size_t row0 = (size_t)(b * 2048 + i0) * 2048 + h * 128;
    const size_t row1 = row0 + (size_t)8 * 2048;
#pragma unroll
    for (int n = 0; n < 16; n++) {
        const int c = n * 8 + 2 * t4;
        uint32_t hh, ll;
        split2(o[n][0] * inv0, o[n][1] * inv0, hh, ll);
        *(uint32_t*)&g_ah[row0 + c] = hh;
        *(uint32_t*)&g_al[row0 + c] = ll;
        split2(o[n][2] * inv1, o[n][3] * inv1, hh, ll);
        *(uint32_t*)&g_ah[row1 + c] = hh;
        *(uint32_t*)&g_al[row1 + c] = ll;
    }
}

// ---------------- launch -------------------------------------------------
extern "C" void kernel_launch(void* const* d_in, const int* in_sizes, int n_in,
                              void* d_out, int out_size) {
    const float* x  = (const float*)d_in[0];
    const float* wq = (const float*)d_in[1];
    const float* wk = (const float*)d_in[2];
    const float* wv = (const float*)d_in[3];
    const float* wo = (const float*)d_in[4];
    float* out = (float*)d_out;

    cudaFuncSetAttribute(attn_mma, cudaFuncAttributeMaxDynamicSharedMemorySize,
                         ATT_SMEM_BYTES);

    rope_tab_kernel<<<512, 256>>>();
    split_planes<0><<<8192, 256>>>(x,  2097152);
    split_planes<1><<<4096, 256>>>(wq, 1048576);
    split_planes<2><<<4096, 256>>>(wk, 1048576);
    split_planes<3><<<4096, 256>>>(wv, 1048576);
    split_planes<4><<<4096, 256>>>(wo, 1048576);

    gemm_mma<1><<<dim3(48, 32), 256>>>(nullptr);
    attn_mma<<<dim3(32, 16), 256, ATT_SMEM_BYTES>>>();
    gemm_mma<0><<<dim3(16, 32), 256>>>(out);
}

// round 16
// speedup vs baseline: 4.9563x; 1.0597x over previous
#include <cuda_runtime.h>
#include <cuda_bf16.h>
#include <math.h>
#include <stdint.h>

// Problem: B=2, S=2048, D=2048, H=16, hd=128
#define SCALE_QK 0.08838834764831843f  // 1/sqrt(128)

// ---------------- scratch (device globals: allocation-free) ----------------
// everything the tensor cores touch lives as split bf16 planes (hi + lo)
#define QKV_ELEMS (2 * 16 * 2048 * 128)
__device__ __align__(16) __nv_bfloat16 g_qh[QKV_ELEMS], g_ql[QKV_ELEMS];
__device__ __align__(16) __nv_bfloat16 g_kh[QKV_ELEMS], g_kl[QKV_ELEMS];
__device__ __align__(16) __nv_bfloat16 g_vh[QKV_ELEMS], g_vl[QKV_ELEMS];
__device__ __align__(16) __nv_bfloat16 g_xh[4096 * 2048], g_xl[4096 * 2048];
__device__ __align__(16) __nv_bfloat16 g_ah[4096 * 2048], g_al[4096 * 2048];  // attn out
__device__ __align__(16) __nv_bfloat16 g_wqh[2048 * 2048], g_wql[2048 * 2048];
__device__ __align__(16) __nv_bfloat16 g_wkh[2048 * 2048], g_wkl[2048 * 2048];
__device__ __align__(16) __nv_bfloat16 g_wvh[2048 * 2048], g_wvl[2048 * 2048];
__device__ __align__(16) __nv_bfloat16 g_woh[2048 * 2048], g_wol[2048 * 2048];
__device__ __align__(16) float g_tab[2048 * 128];     // [s][0..63]=cos, [64..127]=sin

// ---------------- PTX helpers ---------------------------------------------
__device__ __forceinline__ uint32_t smem_u32(const void* p) {
    uint32_t a;
    asm("{ .reg .u64 t; cvta.to.shared.u64 t, %1; cvt.u32.u64 %0, t; }" : "=r"(a) : "l"(p));
    return a;
}

#define LDSM4(r0, r1, r2, r3, addr) \
    asm volatile("ldmatrix.sync.aligned.m8n8.x4.shared.b16 {%0,%1,%2,%3}, [%4];" \
                 : "=r"(r0), "=r"(r1), "=r"(r2), "=r"(r3) : "r"(addr))
#define LDSM4T(r0, r1, r2, r3, addr) \
    asm volatile("ldmatrix.sync.aligned.m8n8.x4.trans.shared.b16 {%0,%1,%2,%3}, [%4];" \
                 : "=r"(r0), "=r"(r1), "=r"(r2), "=r"(r3) : "r"(addr))

// D(16x8,f32) += A(16x16,bf16) x B(16x8,bf16)
#define MMA(d, a, b0, b1) \
    asm volatile("mma.sync.aligned.m16n8k16.row.col.f32.bf16.bf16.f32 " \
                 "{%0,%1,%2,%3}, {%4,%5,%6,%7}, {%8,%9}, {%0,%1,%2,%3};" \
                 : "+f"((d)[0]), "+f"((d)[1]), "+f"((d)[2]), "+f"((d)[3]) \
                 : "r"((a)[0]), "r"((a)[1]), "r"((a)[2]), "r"((a)[3]), \
                   "r"(b0), "r"(b1))

#define CP16(dst, src) \
    asm volatile("cp.async.cg.shared.global [%0], [%1], 16;" :: "r"(dst), "l"(src) : "memory")
#define CP_COMMIT() asm volatile("cp.async.commit_group;" ::: "memory")
#define CP_WAIT0()  asm volatile("cp.async.wait_group 0;" ::: "memory")
#define CP_WAIT1()  asm volatile("cp.async.wait_group 1;" ::: "memory")

// split a float pair into packed bf16 hi + bf16 lo (2-term decomposition)
__device__ __forceinline__ void split2(float x, float y, uint32_t& hi, uint32_t& lo) {
    __nv_bfloat16 xh = __float2bfloat16_rn(x), yh = __float2bfloat16_rn(y);
    float xr = x - __bfloat162float(xh);
    float yr = y - __bfloat162float(yh);
    __nv_bfloat162 hp; hp.x = xh; hp.y = yh;
    __nv_bfloat162 lp = __floats2bfloat162_rn(xr, yr);
    hi = *(uint32_t*)&hp;
    lo = *(uint32_t*)&lp;
}

// ---------------- RoPE table ----------------------------------------------
__global__ void rope_tab_kernel() {
    int idx = blockIdx.x * 256 + threadIdx.x;
    if (idx >= 2048 * 64) return;
    int s = idx >> 6, f = idx & 63;
    double invf = pow(10000.0, -2.0 * (double)f / 128.0);
    double ang = (double)s * invf;
    g_tab[s * 128 + f]      = (float)cos(ang);
    g_tab[s * 128 + 64 + f] = (float)sin(ang);
}

// ---------------- fp32 -> split bf16 plane conversion ----------------------
// Destination selected in DEVICE code (host use of __device__ symbols is UB).
template <int SEL>
__global__ void split_planes(const float* __restrict__ src, int n4) {
    int i = blockIdx.x * 256 + threadIdx.x;
    if (i >= n4) return;
    __nv_bfloat16* dh;
    __nv_bfloat16* dl;
    if      (SEL == 0) { dh = g_xh;  dl = g_xl;  }
    else if (SEL == 1) { dh = g_wqh; dl = g_wql; }
    else if (SEL == 2) { dh = g_wkh; dl = g_wkl; }
    else if (SEL == 3) { dh = g_wvh; dl = g_wvl; }
    else               { dh = g_woh; dl = g_wol; }
    float4 v = ((const float4*)src)[i];
    uint32_t h0, l0, h1, l1;
    split2(v.x, v.y, h0, l0);
    split2(v.z, v.w, h1, l1);
    ((uint2*)dh)[i] = make_uint2(h0, h1);
    ((uint2*)dl)[i] = make_uint2(l0, l1);
}

// ---------------- split-bf16 mma.sync GEMM: C = A @ W^T --------------------
// Tile 128x128, BK=32, 64 stages, cp.async double-buffered (wait_group 1),
// 8 warps (2x4), 64x32/warp, 3 HMMA products. Planes bound in device code.
// Dynamic smem 81920 B/CTA, 2 CTAs/SM. Row stride 80B (conflict-free LDSM:
// r*80 mod 128 = {0,80,32,112,64,16,96,48} -> all 16B chunks distinct).
// MODE 1: A = x planes; nt in [0,48): region -> {wq,wk,wv} planes; RoPE
//         epilogue, writes split planes g_q*/g_k*/g_v* in [b][h][s][d].
// MODE 0: A = attn planes, W = wo planes, fp32 store to out.
#define GPLANE 10240u   // bytes per smem plane: 128 rows x 80B (32 bf16 + 8 pad)
#define GBUF   40960u   // 4 planes (aHi aLo bHi bLo)
#define GEMM_SMEM_BYTES (2 * 40960)

template <int MODE>
__global__ __launch_bounds__(256, 2) void gemm_mma(float* __restrict__ outp)
{
    extern __shared__ __nv_bfloat16 gs[];
    const uint32_t sb = smem_u32(gs);

    const int tid = threadIdx.x;
    const int wid = tid >> 5, lane = tid & 31;
    const int wm = wid >> 2, wn = wid & 3;
    const int nt = blockIdx.x, mt = blockIdx.y;

    int region = 0, nloc;
    const __nv_bfloat16 *Ah, *Al, *Wh, *Wl;
    if (MODE == 0) {
        Ah = g_ah; Al = g_al; Wh = g_woh; Wl = g_wol; nloc = nt;
    } else {
        Ah = g_xh; Al = g_xl;
        region = nt >> 4;
        Wh = (region == 0) ? g_wqh : (region == 1) ? g_wkh : g_wvh;
        Wl = (region == 0) ? g_wql : (region == 1) ? g_wkl : g_wvl;
        nloc = nt & 15;
    }

    const __nv_bfloat16* pA_h = Ah + (size_t)(mt * 128) * 2048;
    const __nv_bfloat16* pA_l = Al + (size_t)(mt * 128) * 2048;
    const __nv_bfloat16* pW_h = Wh + (size_t)(nloc * 128) * 2048;
    const __nv_bfloat16* pW_l = Wl + (size_t)(nloc * 128) * 2048;

    // ldmatrix lane offsets (within one buffer)
    const uint32_t aoff0 = (uint32_t)((wm * 64 + (lane & 15)) * 80 + ((lane >> 4) & 1) * 16);
    const uint32_t aoff1 = aoff0 + GPLANE;
    const uint32_t boff0 = 2u * GPLANE +
        (uint32_t)((wn * 32 + ((lane >> 4) & 1) * 8 + (lane & 7)) * 80 +
                   ((lane >> 3) & 1) * 16);
    const uint32_t boff1 = boff0 + GPLANE;

    float acc[4][4][4];
#pragma unroll
    for (int m = 0; m < 4; m++)
#pragma unroll
        for (int n = 0; n < 4; n++)
#pragma unroll
            for (int e = 0; e < 4; e++) acc[m][n][e] = 0.0f;

    // producer: 2048 16B chunks per stage (4 planes x 512), 8 per thread.
#define LD_STAGE(bufi, kb)                                                      \
    do {                                                                        \
        _Pragma("unroll")                                                       \
        for (int t = 0; t < 8; t++) {                                           \
            const int rem = (t & 1) * 256 + tid;                                \
            const int row = rem >> 2, q = rem & 3;                              \
            uint32_t dst = sb + (bufi) * GBUF + (uint32_t)(t >> 1) * GPLANE +   \
                           (uint32_t)(row * 80 + q * 16);                       \
            const __nv_bfloat16* s_ =                                           \
                ((t >> 1) == 0 ? pA_h : (t >> 1) == 1 ? pA_l                    \
                 : (t >> 1) == 2 ? pW_h : pW_l) +                               \
                (size_t)row * 2048 + (kb) + q * 8;                              \
            CP16(dst, s_);                                                      \
        }                                                                       \
    } while (0)

    LD_STAGE(0u, 0);
    CP_COMMIT();

    for (int s = 0; s < 64; ++s) {
        const uint32_t buf = (uint32_t)(s & 1);
        if (s < 63) {
            LD_STAGE(buf ^ 1u, (s + 1) * 32);
            CP_COMMIT();
            CP_WAIT1();
        } else {
            CP_WAIT0();
        }
        __syncthreads();

        const uint32_t bb = sb + buf * GBUF;
#pragma unroll
        for (int ks = 0; ks < 2; ++ks) {
            const uint32_t ko = (uint32_t)(ks * 32);
            uint32_t ah[4][4], al[4][4];
#pragma unroll
            for (int m = 0; m < 4; m++) {
                LDSM4(ah[m][0], ah[m][1], ah[m][2], ah[m][3],
                      bb + aoff0 + (uint32_t)(m * 1280) + ko);
                LDSM4(al[m][0], al[m][1], al[m][2], al[m][3],
                      bb + aoff1 + (uint32_t)(m * 1280) + ko);
            }
#pragma unroll
            for (int ng = 0; ng < 2; ++ng) {
                uint32_t bh[4], bl[4];
                LDSM4(bh[0], bh[1], bh[2], bh[3],
                      bb + boff0 + (uint32_t)(ng * 1280) + ko);
                LDSM4(bl[0], bl[1], bl[2], bl[3],
                      bb + boff1 + (uint32_t)(ng * 1280) + ko);
#pragma unroll
                for (int m = 0; m < 4; m++) {
                    MMA(acc[m][2 * ng], ah[m], bh[0], bh[1]);      // hi*hi
                    MMA(acc[m][2 * ng], ah[m], bl[0], bl[1]);      // hi*lo
                    MMA(acc[m][2 * ng], al[m], bh[0], bh[1]);      // lo*hi
                    MMA(acc[m][2 * ng + 1], ah[m], bh[2], bh[3]);
                    MMA(acc[m][2 * ng + 1], ah[m], bl[2], bl[3]);
                    MMA(acc[m][2 * ng + 1], al[m], bh[2], bh[3]);
                }
            }
        }
        __syncthreads();   // all warps done with buf before it is refilled
    }
#undef LD_STAGE

    // ---- epilogue (identical to R15) ----
    const int qr = lane >> 2, qc = 2 * (lane & 3);
#pragma unroll
    for (int m = 0; m < 4; m++) {
        const int r0 = mt * 128 + wm * 64 + m * 16 + qr;
#pragma unroll
        for (int half = 0; half < 2; half++) {
            const int r = r0 + half * 8;
            if (MODE == 0) {
                float* drow = outp + (size_t)r * 2048 + nt * 128;
#pragma unroll
                for (int n = 0; n < 4; n++) {
                    const int col = wn * 32 + n * 8 + qc;
                    *(float2*)&drow[col] =
                        make_float2(acc[m][n][2 * half], acc[m][n][2 * half + 1]);
                }
            } else {
                const int b = r >> 11, spos = r & 2047, h = nt & 15;
                __nv_bfloat16* dh = (region == 0) ? g_qh : (region == 1) ? g_kh : g_vh;
                __nv_bfloat16* dl = (region == 0) ? g_ql : (region == 1) ? g_kl : g_vl;
                const size_t rowb = ((size_t)(b * 16 + h) * 2048 + spos) * 128;
                const float* tab = g_tab + spos * 128;
#pragma unroll
                for (int n = 0; n < 4; n++) {
                    const int col = wn * 32 + n * 8 + qc;
                    float v0 = acc[m][n][2 * half], v1 = acc[m][n][2 * half + 1];
                    float2 ov;
                    if (region < 2) {  // RoPE rotate pair (2f, 2f+1)
                        const int f = col >> 1;
                        float c = tab[f], sn = tab[64 + f];
                        ov = make_float2(v0 * c - v1 * sn, v0 * sn + v1 * c);
                    } else {
                        ov = make_float2(v0, v1);
                    }
                    uint32_t hh, ll;
                    split2(ov.x, ov.y, hh, ll);
                    *(uint32_t*)&dh[rowb + col] = hh;
                    *(uint32_t*)&dl[rowb + col] = ll;
                }
            }
        }
    }
}

// ---------------- Flash attention: split-bf16 mma.sync (unchanged) --------
// CTA: 128 q-rows x 64-kv tiles, 8 warps x 16 q-rows. Causal, heavy-first.
#define AQS  17408            // 128*136 elems, one Q plane
#define AKVS 8704             // 64*136 elems, one K/V plane
#define ATT_SMEM_BYTES ((2 * AQS + 2 * 4 * AKVS) * 2)

__device__ __forceinline__ void ldkv(uint32_t sb, int buf, size_t kvoff, int tid) {
#pragma unroll
    for (int t = 0; t < 16; t++) {
        const int plane = t >> 2;
        int rem = (t & 3) * 256 + tid;
        int row = rem >> 4, ch = rem & 15;
        uint32_t dst = sb +
            (uint32_t)((2 * AQS + buf * 4 * AKVS + plane * AKVS + row * 136 + ch * 8) * 2);
        const __nv_bfloat16* src =
            ((plane == 0) ? g_kh : (plane == 1) ? g_kl : (plane == 2) ? g_vh : g_vl)
            + kvoff + row * 128 + ch * 8;
        CP16(dst, src);
    }
}

__global__ __launch_bounds__(256, 1) void attn_mma() {
    extern __shared__ __nv_bfloat16 smb[];
    const uint32_t sb = smem_u32(smb);
    const int tid = threadIdx.x;
    const int lane = tid & 31, w = tid >> 5;
    const int t4 = lane & 3, r = lane >> 2;
    const int bh = blockIdx.x;
    const int qt = 15 - blockIdx.y;            // heavy diagonals first
    const int kvmax = 2 * qt + 2;
    const size_t bh_off = (size_t)bh * 2048 * 128;
    const size_t qoff = bh_off + (size_t)qt * 128 * 128;

#pragma unroll
    for (int t = 0; t < 16; t++) {
        const int plane = t >> 3;
        int rem = (t & 7) * 256 + tid;
        int row = rem >> 4, ch = rem & 15;
        uint32_t dst = sb + (uint32_t)((plane * AQS + row * 136 + ch * 8) * 2);
        const __nv_bfloat16* src = (plane ? g_ql : g_qh) + qoff + row * 128 + ch * 8;
        CP16(dst, src);
    }
    ldkv(sb, 0, bh_off, tid);
    CP_COMMIT();

    float o[16][4];
#pragma unroll
    for (int n = 0; n < 16; n++)
#pragma unroll
        for (int e = 0; e < 4; e++) o[n][e] = 0.0f;
    float m0 = -INFINITY, m1 = -INFINITY, l0 = 0.0f, l1 = 0.0f;

    uint32_t qaddr[2];
#pragma unroll
    for (int p = 0; p < 2; p++)
        qaddr[p] = sb + (uint32_t)((p * AQS + (w * 16 + (lane & 15)) * 136 +
                                    (lane >> 4) * 8) * 2);
    const uint32_t krow = (uint32_t)(((8 * (lane >> 4) + (lane & 7)) * 136 +
                                      ((lane >> 3) & 1) * 8) * 2);
    const uint32_t vrow = (uint32_t)((((lane & 7) + 8 * ((lane >> 3) & 1)) * 136 +
                                      (lane >> 4) * 8) * 2);
    const int i0 = qt * 128 + w * 16 + r;
    const int i1 = i0 + 8;

    for (int kv = 0; kv < kvmax; ++kv) {
        const int buf = kv & 1;
        if (kv + 1 < kvmax) {
            ldkv(sb, buf ^ 1, bh_off + (size_t)(kv + 1) * 64 * 128, tid);
            CP_COMMIT();
            CP_WAIT1();
        } else {
            CP_WAIT0();
        }
        __syncthreads();

        const uint32_t kb0 = sb + (uint32_t)((2 * AQS + buf * 4 * AKVS) * 2) + krow;
        const uint32_t kb1 = kb0 + (uint32_t)(AKVS * 2);
        const uint32_t vb0 = sb + (uint32_t)((2 * AQS + buf * 4 * AKVS + 2 * AKVS) * 2) + vrow;
        const uint32_t vb1 = vb0 + (uint32_t)(AKVS * 2);

        // ---- QK^T: 3-product split bf16 ----
        float sc[8][4];
#pragma unroll
        for (int n = 0; n < 8; n++)
#pragma unroll
            for (int e = 0; e < 4; e++) sc[n][e] = 0.0f;

#pragma unroll
        for (int ks = 0; ks < 8; ++ks) {
            uint32_t ah[4], al[4];
            LDSM4(ah[0], ah[1], ah[2], ah[3], qaddr[0] + ks * 32);
            LDSM4(al[0], al[1], al[2], al[3], qaddr[1] + ks * 32);
#pragma unroll
            for (int jg = 0; jg < 4; ++jg) {
                uint32_t kh[4], kl[4];
                const uint32_t off = (uint32_t)(jg * 4352 + ks * 32);
                LDSM4(kh[0], kh[1], kh[2], kh[3], kb0 + off);
                LDSM4(kl[0], kl[1], kl[2], kl[3], kb1 + off);
                MMA(sc[2 * jg], ah, kh[0], kh[1]);
                MMA(sc[2 * jg], ah, kl[0], kl[1]);
                MMA(sc[2 * jg], al, kh[0], kh[1]);
                MMA(sc[2 * jg + 1], ah, kh[2], kh[3]);
                MMA(sc[2 * jg + 1], ah, kl[2], kl[3]);
                MMA(sc[2 * jg + 1], al, kh[2], kh[3]);
            }
        }

        // ---- online softmax ----
        const bool needmask = (kv * 64 + 63) > (qt * 128 + w * 16);
        float mx0 = -INFINITY, mx1 = -INFINITY;
#pragma unroll
        for (int n = 0; n < 8; n++) {
#pragma unroll
            for (int e = 0; e < 4; e++) {
                float s = sc[n][e] * SCALE_QK;
                if (needmask) {
                    int jc = kv * 64 + n * 8 + 2 * t4 + (e & 1);
                    int ir = (e < 2) ? i0 : i1;
                    if (jc > ir) s = -1e30f;
                }
                sc[n][e] = s;
            }
            mx0 = fmaxf(mx0, fmaxf(sc[n][0], sc[n][1]));
            mx1 = fmaxf(mx1, fmaxf(sc[n][2], sc[n][3]));
        }
        mx0 = fmaxf(mx0, __shfl_xor_sync(0xffffffffu, mx0, 1));
        mx0 = fmaxf(mx0, __shfl_xor_sync(0xffffffffu, mx0, 2));
        mx1 = fmaxf(mx1, __shfl_xor_sync(0xffffffffu, mx1, 1));
        mx1 = fmaxf(mx1, __shfl_xor_sync(0xffffffffu, mx1, 2));

        const float mn0 = fmaxf(m0, mx0), mn1 = fmaxf(m1, mx1);
        const float a0 = __expf(m0 - mn0), a1 = __expf(m1 - mn1);
        m0 = mn0; m1 = mn1;
        float rs0 = 0.0f, rs1 = 0.0f;
#pragma unroll
        for (int n = 0; n < 8; n++) {
            float p0 = __expf(sc[n][0] - mn0), p1 = __expf(sc[n][1] - mn0);
            float p2 = __expf(sc[n][2] - mn1), p3 = __expf(sc[n][3] - mn1);
            sc[n][0] = p0; sc[n][1] = p1; sc[n][2] = p2; sc[n][3] = p3;
            rs0 += p0 + p1; rs1 += p2 + p3;
        }
        rs0 += __shfl_xor_sync(0xffffffffu, rs0, 1);
        rs0 += __shfl_xor_sync(0xffffffffu, rs0, 2);
        rs1 += __shfl_xor_sync(0xffffffffu, rs1, 1);
        rs1 += __shfl_xor_sync(0xffffffffu, rs1, 2);
        l0 = l0 * a0 + rs0;
        l1 = l1 * a1 + rs1;

#pragma unroll
        for (int n = 0; n < 16; n++) {
            o[n][0] *= a0; o[n][1] *= a0;
            o[n][2] *= a1; o[n][3] *= a1;
        }

        // pack P -> bf16 hi/lo A-fragments (c-layout == A-layout identity)
        uint32_t ph0[8], pl0[8], ph1[8], pl1[8];
#pragma unroll
        for (int n = 0; n < 8; n++) {
            split2(sc[n][0], sc[n][1], ph0[n], pl0[n]);
            split2(sc[n][2], sc[n][3], ph1[n], pl1[n]);
        }

        // ---- P @ V: 3-product split bf16 ----
#pragma unroll
        for (int ks = 0; ks < 4; ++ks) {
            uint32_t aPh[4] = {ph0[2 * ks], ph1[2 * ks], ph0[2 * ks + 1], ph1[2 * ks + 1]};
            uint32_t aPl[4] = {pl0[2 * ks], pl1[2 * ks], pl0[2 * ks + 1], pl1[2 * ks + 1]};
#pragma unroll
            for (int ng = 0; ng < 8; ++ng) {
                uint32_t vh[4], vl[4];
                const uint32_t off = (uint32_t)(ks * 4352 + ng * 32);
                LDSM4T(vh[0], vh[1], vh[2], vh[3], vb0 + off);
                LDSM4T(vl[0], vl[1], vl[2], vl[3], vb1 + off);
                MMA(o[2 * ng], aPh, vh[0], vh[1]);
                MMA(o[2 * ng], aPh, vl[0], vl[1]);
                MMA(o[2 * ng], aPl, vh[0], vh[1]);
                MMA(o[2 * ng + 1], aPh, vh[2], vh[3]);
                MMA(o[2 * ng + 1], aPh, vl[2], vl[3]);
                MMA(o[2 * ng + 1], aPl, vh[2], vh[3]);
            }
        }
        __syncthreads();
    }

    // ---- finalize: divide by l, write split planes for the WO GEMM ----
    const float inv0 = 1.0f / l0, inv1 = 1.0f / l1;
    const int b = bh >> 4, h = bh & 15;
    const size_t row0 = (size_t)(b * 2048 + i0) * 2048 + h * 128;
    const size_t row1 = row0 + (size_t)8 * 2048;
#pragma unroll
    for (int n = 0; n < 16; n++) {
        const int c = n * 8 + 2 * t4;
        uint32_t hh, ll;
        split2(o[n][0] * inv0, o[n][1] * inv0, hh, ll);
        *(uint32_t*)&g_ah[row0 + c] = hh;
        *(uint32_t*)&g_al[row0 + c] = ll;
        split2(o[n][2] * inv1, o[n][3] * inv1, hh, ll);
        *(uint32_t*)&g_ah[row1 + c] = hh;
        *(uint32_t*)&g_al[row1 + c] = ll;
    }
}

// ---------------- launch -------------------------------------------------
extern "C" void kernel_launch(void* const* d_in, const int* in_sizes, int n_in,
                              void* d_out, int out_size) {
    const float* x  = (const float*)d_in[0];
    const float* wq = (const float*)d_in[1];
    const float* wk = (const float*)d_in[2];
    const float* wv = (const float*)d_in[3];
    const float* wo = (const float*)d_in[4];
    float* out = (float*)d_out;

    cudaFuncSetAttribute(attn_mma, cudaFuncAttributeMaxDynamicSharedMemorySize,
                         ATT_SMEM_BYTES);
    cudaFuncSetAttribute(gemm_mma<1>, cudaFuncAttributeMaxDynamicSharedMemorySize,
                         GEMM_SMEM_BYTES);
    cudaFuncSetAttribute(gemm_mma<0>, cudaFuncAttributeMaxDynamicSharedMemorySize,
                         GEMM_SMEM_BYTES);

    rope_tab_kernel<<<512, 256>>>();
    split_planes<0><<<8192, 256>>>(x,  2097152);
    split_planes<1><<<4096, 256>>>(wq, 1048576);
    split_planes<2><<<4096, 256>>>(wk, 1048576);
    split_planes<3><<<4096, 256>>>(wv, 1048576);
    split_planes<4><<<4096, 256>>>(wo, 1048576);

    gemm_mma<1><<<dim3(48, 32), 256, GEMM_SMEM_BYTES>>>(nullptr);
    attn_mma<<<dim3(32, 16), 256, ATT_SMEM_BYTES>>>();
    gemm_mma<0><<<dim3(16, 32), 256, GEMM_SMEM_BYTES>>>(out);
}

// round 17
// speedup vs baseline: 5.1011x; 1.0292x over previous
#include <cuda_runtime.h>
#include <cuda_bf16.h>
#include <math.h>
#include <stdint.h>

// Problem: B=2, S=2048, D=2048, H=16, hd=128
#define SCALE_QK 0.08838834764831843f  // 1/sqrt(128)

// ---------------- scratch (device globals: allocation-free) ----------------
// everything the tensor cores touch lives as split bf16 planes (hi + lo)
#define QKV_ELEMS (2 * 16 * 2048 * 128)
__device__ __align__(16) __nv_bfloat16 g_qh[QKV_ELEMS], g_ql[QKV_ELEMS];
__device__ __align__(16) __nv_bfloat16 g_kh[QKV_ELEMS], g_kl[QKV_ELEMS];
__device__ __align__(16) __nv_bfloat16 g_vh[QKV_ELEMS], g_vl[QKV_ELEMS];
__device__ __align__(16) __nv_bfloat16 g_xh[4096 * 2048], g_xl[4096 * 2048];
__device__ __align__(16) __nv_bfloat16 g_ah[4096 * 2048], g_al[4096 * 2048];  // attn out
__device__ __align__(16) __nv_bfloat16 g_wqh[2048 * 2048], g_wql[2048 * 2048];
__device__ __align__(16) __nv_bfloat16 g_wkh[2048 * 2048], g_wkl[2048 * 2048];
__device__ __align__(16) __nv_bfloat16 g_wvh[2048 * 2048], g_wvl[2048 * 2048];
__device__ __align__(16) __nv_bfloat16 g_woh[2048 * 2048], g_wol[2048 * 2048];
__device__ __align__(16) float g_tab[2048 * 128];     // [s][0..63]=cos, [64..127]=sin

// ---------------- PTX helpers ---------------------------------------------
__device__ __forceinline__ uint32_t smem_u32(const void* p) {
    uint32_t a;
    asm("{ .reg .u64 t; cvta.to.shared.u64 t, %1; cvt.u32.u64 %0, t; }" : "=r"(a) : "l"(p));
    return a;
}

#define LDSM4(r0, r1, r2, r3, addr) \
    asm volatile("ldmatrix.sync.aligned.m8n8.x4.shared.b16 {%0,%1,%2,%3}, [%4];" \
                 : "=r"(r0), "=r"(r1), "=r"(r2), "=r"(r3) : "r"(addr))
#define LDSM4T(r0, r1, r2, r3, addr) \
    asm volatile("ldmatrix.sync.aligned.m8n8.x4.trans.shared.b16 {%0,%1,%2,%3}, [%4];" \
                 : "=r"(r0), "=r"(r1), "=r"(r2), "=r"(r3) : "r"(addr))

// D(16x8,f32) += A(16x16,bf16) x B(16x8,bf16)
#define MMA(d, a, b0, b1) \
    asm volatile("mma.sync.aligned.m16n8k16.row.col.f32.bf16.bf16.f32 " \
                 "{%0,%1,%2,%3}, {%4,%5,%6,%7}, {%8,%9}, {%0,%1,%2,%3};" \
                 : "+f"((d)[0]), "+f"((d)[1]), "+f"((d)[2]), "+f"((d)[3]) \
                 : "r"((a)[0]), "r"((a)[1]), "r"((a)[2]), "r"((a)[3]), \
                   "r"(b0), "r"(b1))

#define CP16(dst, src) \
    asm volatile("cp.async.cg.shared.global [%0], [%1], 16;" :: "r"(dst), "l"(src) : "memory")
#define CP_COMMIT() asm volatile("cp.async.commit_group;" ::: "memory")
#define CP_WAIT0()  asm volatile("cp.async.wait_group 0;" ::: "memory")

// split a float pair into packed bf16 hi + bf16 lo (2-term decomposition)
__device__ __forceinline__ void split2(float x, float y, uint32_t& hi, uint32_t& lo) {
    __nv_bfloat16 xh = __float2bfloat16_rn(x), yh = __float2bfloat16_rn(y);
    float xr = x - __bfloat162float(xh);
    float yr = y - __bfloat162float(yh);
    __nv_bfloat162 hp; hp.x = xh; hp.y = yh;
    __nv_bfloat162 lp = __floats2bfloat162_rn(xr, yr);
    hi = *(uint32_t*)&hp;
    lo = *(uint32_t*)&lp;
}

// ---------------- RoPE table ----------------------------------------------
__global__ void rope_tab_kernel() {
    int idx = blockIdx.x * 256 + threadIdx.x;
    if (idx >= 2048 * 64) return;
    int s = idx >> 6, f = idx & 63;
    double invf = pow(10000.0, -2.0 * (double)f / 128.0);
    double ang = (double)s * invf;
    g_tab[s * 128 + f]      = (float)cos(ang);
    g_tab[s * 128 + 64 + f] = (float)sin(ang);
}

// ---------------- fp32 -> split bf16 planes, all 5 tensors in one launch ---
// Sources are harness pointers (legal args); dests bound in device code.
#define N4_X  2097152
#define N4_W  1048576
__global__ void split_all(const float* __restrict__ x,  const float* __restrict__ wq,
                          const float* __restrict__ wk, const float* __restrict__ wv,
                          const float* __restrict__ wo) {
    int i = blockIdx.x * 256 + threadIdx.x;
    const float* src;
    __nv_bfloat16 *dh, *dl;
    int off;
    if (i < N4_X)                    { src = x;  dh = g_xh;  dl = g_xl;  off = i; }
    else if (i < N4_X + 1 * N4_W)    { src = wq; dh = g_wqh; dl = g_wql; off = i - N4_X; }
    else if (i < N4_X + 2 * N4_W)    { src = wk; dh = g_wkh; dl = g_wkl; off = i - N4_X - 1 * N4_W; }
    else if (i < N4_X + 3 * N4_W)    { src = wv; dh = g_wvh; dl = g_wvl; off = i - N4_X - 2 * N4_W; }
    else                             { src = wo; dh = g_woh; dl = g_wol; off = i - N4_X - 3 * N4_W; }
    float4 v = ((const float4*)src)[off];
    uint32_t h0, l0, h1, l1;
    split2(v.x, v.y, h0, l0);
    split2(v.z, v.w, h1, l1);
    ((uint2*)dh)[off] = make_uint2(h0, h1);
    ((uint2*)dl)[off] = make_uint2(l0, l1);
}
#define SPLIT_ALL_BLOCKS ((N4_X + 4 * N4_W) / 256)   // 24576

// ---------------- split-bf16 mma.sync GEMM: C = A @ W^T --------------------
// Tile 128x128, BK=32, 64 stages, cp.async double-buffered, ONE barrier per
// stage (next-stage loads issued after the leading barrier, which already
// proves all warps are done reading the buffer being refilled).
// 8 warps (2x4), 64x32/warp, 3 HMMA products, 2 CTAs/SM, 80B row stride.
// MODE 1: A = x planes; nt in [0,48): region -> {wq,wk,wv} planes; RoPE
//         epilogue, writes split planes g_q*/g_k*/g_v* in [b][h][s][d].
// MODE 0: A = attn planes, W = wo planes, fp32 store to out.
#define GPLANE 10240u   // bytes per smem plane: 128 rows x 80B (32 bf16 + 8 pad)
#define GBUF   40960u   // 4 planes (aHi aLo bHi bLo)
#define GEMM_SMEM_BYTES (2 * 40960)

template <int MODE>
__global__ __launch_bounds__(256, 2) void gemm_mma(float* __restrict__ outp)
{
    extern __shared__ __nv_bfloat16 gs[];
    const uint32_t sb = smem_u32(gs);

    const int tid = threadIdx.x;
    const int wid = tid >> 5, lane = tid & 31;
    const int wm = wid >> 2, wn = wid & 3;
    const int nt = blockIdx.x, mt = blockIdx.y;

    int region = 0, nloc;
    const __nv_bfloat16 *Ah, *Al, *Wh, *Wl;
    if (MODE == 0) {
        Ah = g_ah; Al = g_al; Wh = g_woh; Wl = g_wol; nloc = nt;
    } else {
        Ah = g_xh; Al = g_xl;
        region = nt >> 4;
        Wh = (region == 0) ? g_wqh : (region == 1) ? g_wkh : g_wvh;
        Wl = (region == 0) ? g_wql : (region == 1) ? g_wkl : g_wvl;
        nloc = nt & 15;
    }

    const __nv_bfloat16* pA_h = Ah + (size_t)(mt * 128) * 2048;
    const __nv_bfloat16* pA_l = Al + (size_t)(mt * 128) * 2048;
    const __nv_bfloat16* pW_h = Wh + (size_t)(nloc * 128) * 2048;
    const __nv_bfloat16* pW_l = Wl + (size_t)(nloc * 128) * 2048;

    // ldmatrix lane offsets (within one buffer)
    const uint32_t aoff0 = (uint32_t)((wm * 64 + (lane & 15)) * 80 + ((lane >> 4) & 1) * 16);
    const uint32_t aoff1 = aoff0 + GPLANE;
    const uint32_t boff0 = 2u * GPLANE +
        (uint32_t)((wn * 32 + ((lane >> 4) & 1) * 8 + (lane & 7)) * 80 +
                   ((lane >> 3) & 1) * 16);
    const uint32_t boff1 = boff0 + GPLANE;

    float acc[4][4][4];
#pragma unroll
    for (int m = 0; m < 4; m++)
#pragma unroll
        for (int n = 0; n < 4; n++)
#pragma unroll
            for (int e = 0; e < 4; e++) acc[m][n][e] = 0.0f;

    // producer: 2048 16B chunks per stage (4 planes x 512), 8 per thread.
#define LD_STAGE(bufi, kb)                                                      \
    do {                                                                        \
        _Pragma("unroll")                                                       \
        for (int t = 0; t < 8; t++) {                                           \
            const int rem = (t & 1) * 256 + tid;                                \
            const int row = rem >> 2, q = rem & 3;                              \
            uint32_t dst = sb + (bufi) * GBUF + (uint32_t)(t >> 1) * GPLANE +   \
                           (uint32_t)(row * 80 + q * 16);                       \
            const __nv_bfloat16* s_ =                                           \
                ((t >> 1) == 0 ? pA_h : (t >> 1) == 1 ? pA_l                    \
                 : (t >> 1) == 2 ? pW_h : pW_l) +                               \
                (size_t)row * 2048 + (kb) + q * 8;                              \
            CP16(dst, s_);                                                      \
        }                                                                       \
    } while (0)

    LD_STAGE(0u, 0);
    CP_COMMIT();

    for (int s = 0; s < 64; ++s) {
        const uint32_t buf = (uint32_t)(s & 1);
        CP_WAIT0();          // stage-s group landed (only pending group)
        __syncthreads();     // publish stage-s data; all warps done with s-1
        if (s < 63) {        // safe: buf^1 last read in stage s-1, all past barrier
            LD_STAGE(buf ^ 1u, (s + 1) * 32);
            CP_COMMIT();
        }

        const uint32_t bb = sb + buf * GBUF;
#pragma unroll
        for (int ks = 0; ks < 2; ++ks) {
            const uint32_t ko = (uint32_t)(ks * 32);
            uint32_t ah[4][4], al[4][4];
#pragma unroll
            for (int m = 0; m < 4; m++) {
                LDSM4(ah[m][0], ah[m][1], ah[m][2], ah[m][3],
                      bb + aoff0 + (uint32_t)(m * 1280) + ko);
                LDSM4(al[m][0], al[m][1], al[m][2], al[m][3],
                      bb + aoff1 + (uint32_t)(m * 1280) + ko);
            }
#pragma unroll
            for (int ng = 0; ng < 2; ++ng) {
                uint32_t bh[4], bl[4];
                LDSM4(bh[0], bh[1], bh[2], bh[3],
                      bb + boff0 + (uint32_t)(ng * 1280) + ko);
                LDSM4(bl[0], bl[1], bl[2], bl[3],
                      bb + boff1 + (uint32_t)(ng * 1280) + ko);
#pragma unroll
                for (int m = 0; m < 4; m++) {
                    MMA(acc[m][2 * ng], ah[m], bh[0], bh[1]);      // hi*hi
                    MMA(acc[m][2 * ng], ah[m], bl[0], bl[1]);      // hi*lo
                    MMA(acc[m][2 * ng], al[m], bh[0], bh[1]);      // lo*hi
                    MMA(acc[m][2 * ng + 1], ah[m], bh[2], bh[3]);
                    MMA(acc[m][2 * ng + 1], ah[m], bl[2], bl[3]);
                    MMA(acc[m][2 * ng + 1], al[m], bh[2], bh[3]);
                }
            }
        }
    }
#undef LD_STAGE

    // ---- epilogue (identical numerics) ----
    const int qr = lane >> 2, qc = 2 * (lane & 3);
#pragma unroll
    for (int m = 0; m < 4; m++) {
        const int r0 = mt * 128 + wm * 64 + m * 16 + qr;
#pragma unroll
        for (int half = 0; half < 2; half++) {
            const int r = r0 + half * 8;
            if (MODE == 0) {
                float* drow = outp + (size_t)r * 2048 + nt * 128;
#pragma unroll
                for (int n = 0; n < 4; n++) {
                    const int col = wn * 32 + n * 8 + qc;
                    *(float2*)&drow[col] =
                        make_float2(acc[m][n][2 * half], acc[m][n][2 * half + 1]);
                }
            } else {
                const int b = r >> 11, spos = r & 2047, h = nt & 15;
                __nv_bfloat16* dh = (region == 0) ? g_qh : (region == 1) ? g_kh : g_vh;
                __nv_bfloat16* dl = (region == 0) ? g_ql : (region == 1) ? g_kl : g_vl;
                const size_t rowb = ((size_t)(b * 16 + h) * 2048 + spos) * 128;
                const float* tab = g_tab + spos * 128;
#pragma unroll
                for (int n = 0; n < 4; n++) {
                    const int col = wn * 32 + n * 8 + qc;
                    float v0 = acc[m][n][2 * half], v1 = acc[m][n][2 * half + 1];
                    float2 ov;
                    if (region < 2) {  // RoPE rotate pair (2f, 2f+1)
                        const int f = col >> 1;
                        float c = tab[f], sn = tab[64 + f];
                        ov = make_float2(v0 * c - v1 * sn, v0 * sn + v1 * c);
                    } else {
                        ov = make_float2(v0, v1);
                    }
                    uint32_t hh, ll;
                    split2(ov.x, ov.y, hh, ll);
                    *(uint32_t*)&dh[rowb + col] = hh;
                    *(uint32_t*)&dl[rowb + col] = ll;
                }
            }
        }
    }
}

// ---------------- Flash attention: split-bf16 mma.sync --------------------
// CTA: 128 q-rows x 64-kv tiles, 8 warps x 16 q-rows. Causal, heavy-first.
// Single barrier per kv iteration (same reordering as the GEMM).
#define AQS  17408            // 128*136 elems, one Q plane
#define AKVS 8704             // 64*136 elems, one K/V plane
#define ATT_SMEM_BYTES ((2 * AQS + 2 * 4 * AKVS) * 2)

__device__ __forceinline__ void ldkv(uint32_t sb, int buf, size_t kvoff, int tid) {
#pragma unroll
    for (int t = 0; t < 16; t++) {
        const int plane = t >> 2;
        int rem = (t & 3) * 256 + tid;
        int row = rem >> 4, ch = rem & 15;
        uint32_t dst = sb +
            (uint32_t)((2 * AQS + buf * 4 * AKVS + plane * AKVS + row * 136 + ch * 8) * 2);
        const __nv_bfloat16* src =
            ((plane == 0) ? g_kh : (plane == 1) ? g_kl : (plane == 2) ? g_vh : g_vl)
            + kvoff + row * 128 + ch * 8;
        CP16(dst, src);
    }
}

__global__ __launch_bounds__(256, 1) void attn_mma() {
    extern __shared__ __nv_bfloat16 smb[];
    const uint32_t sb = smem_u32(smb);
    const int tid = threadIdx.x;
    const int lane = tid & 31, w = tid >> 5;
    const int t4 = lane & 3, r = lane >> 2;
    const int bh = blockIdx.x;
    const int qt = 15 - blockIdx.y;            // heavy diagonals first
    const int kvmax = 2 * qt + 2;
    const size_t bh_off = (size_t)bh * 2048 * 128;
    const size_t qoff = bh_off + (size_t)qt * 128 * 128;

#pragma unroll
    for (int t = 0; t < 16; t++) {
        const int plane = t >> 3;
        int rem = (t & 7) * 256 + tid;
        int row = rem >> 4, ch = rem & 15;
        uint32_t dst = sb + (uint32_t)((plane * AQS + row * 136 + ch * 8) * 2);
        const __nv_bfloat16* src = (plane ? g_ql : g_qh) + qoff + row * 128 + ch * 8;
        CP16(dst, src);
    }
    ldkv(sb, 0, bh_off, tid);
    CP_COMMIT();

    float o[16][4];
#pragma unroll
    for (int n = 0; n < 16; n++)
#pragma unroll
        for (int e = 0; e < 4; e++) o[n][e] = 0.0f;
    float m0 = -INFINITY, m1 = -INFINITY, l0 = 0.0f, l1 = 0.0f;

    uint32_t qaddr[2];
#pragma unroll
    for (int p = 0; p < 2; p++)
        qaddr[p] = sb + (uint32_t)((p * AQS + (w * 16 + (lane & 15)) * 136 +
                                    (lane >> 4) * 8) * 2);
    const uint32_t krow = (uint32_t)(((8 * (lane >> 4) + (lane & 7)) * 136 +
                                      ((lane >> 3) & 1) * 8) * 2);
    const uint32_t vrow = (uint32_t)((((lane & 7) + 8 * ((lane >> 3) & 1)) * 136 +
                                      (lane >> 4) * 8) * 2);
    const int i0 = qt * 128 + w * 16 + r;
    const int i1 = i0 + 8;

    for (int kv = 0; kv < kvmax; ++kv) {
        const int buf = kv & 1;
        CP_WAIT0();          // this tile's (and Q's, at kv=0) loads landed
        __syncthreads();     // publish; all warps done reading buf^1 (kv-1)
        if (kv + 1 < kvmax) {
            ldkv(sb, buf ^ 1, bh_off + (size_t)(kv + 1) * 64 * 128, tid);
            CP_COMMIT();
        }

        const uint32_t kb0 = sb + (uint32_t)((2 * AQS + buf * 4 * AKVS) * 2) + krow;
        const uint32_t kb1 = kb0 + (uint32_t)(AKVS * 2);
        const uint32_t vb0 = sb + (uint32_t)((2 * AQS + buf * 4 * AKVS + 2 * AKVS) * 2) + vrow;
        const uint32_t vb1 = vb0 + (uint32_t)(AKVS * 2);

        // ---- QK^T: 3-product split bf16 ----
        float sc[8][4];
#pragma unroll
        for (int n = 0; n < 8; n++)
#pragma unroll
            for (int e = 0; e < 4; e++) sc[n][e] = 0.0f;

#pragma unroll
        for (int ks = 0; ks < 8; ++ks) {
            uint32_t ah[4], al[4];
            LDSM4(ah[0], ah[1], ah[2], ah[3], qaddr[0] + ks * 32);
            LDSM4(al[0], al[1], al[2], al[3], qaddr[1] + ks * 32);
#pragma unroll
            for (int jg = 0; jg < 4; ++jg) {
                uint32_t kh[4], kl[4];
                const uint32_t off = (uint32_t)(jg * 4352 + ks * 32);
                LDSM4(kh[0], kh[1], kh[2], kh[3], kb0 + off);
                LDSM4(kl[0], kl[1], kl[2], kl[3], kb1 + off);
                MMA(sc[2 * jg], ah, kh[0], kh[1]);
                MMA(sc[2 * jg], ah, kl[0], kl[1]);
                MMA(sc[2 * jg], al, kh[0], kh[1]);
                MMA(sc[2 * jg + 1], ah, kh[2], kh[3]);
                MMA(sc[2 * jg + 1], ah, kl[2], kl[3]);
                MMA(sc[2 * jg + 1], al, kh[2], kh[3]);
            }
        }

        // ---- online softmax ----
        const bool needmask = (kv * 64 + 63) > (qt * 128 + w * 16);
        float mx0 = -INFINITY, mx1 = -INFINITY;
#pragma unroll
        for (int n = 0; n < 8; n++) {
#pragma unroll
            for (int e = 0; e < 4; e++) {
                float s = sc[n][e] * SCALE_QK;
                if (needmask) {
                    int jc = kv * 64 + n * 8 + 2 * t4 + (e & 1);
                    int ir = (e < 2) ? i0 : i1;
                    if (jc > ir) s = -1e30f;
                }
                sc[n][e] = s;
            }
            mx0 = fmaxf(mx0, fmaxf(sc[n][0], sc[n][1]));
            mx1 = fmaxf(mx1, fmaxf(sc[n][2], sc[n][3]));
        }
        mx0 = fmaxf(mx0, __shfl_xor_sync(0xffffffffu, mx0, 1));
        mx0 = fmaxf(mx0, __shfl_xor_sync(0xffffffffu, mx0, 2));
        mx1 = fmaxf(mx1, __shfl_xor_sync(0xffffffffu, mx1, 1));
        mx1 = fmaxf(mx1, __shfl_xor_sync(0xffffffffu, mx1, 2));

        const float mn0 = fmaxf(m0, mx0), mn1 = fmaxf(m1, mx1);
        const float a0 = __expf(m0 - mn0), a1 = __expf(m1 - mn1);
        m0 = mn0; m1 = mn1;
        float rs0 = 0.0f, rs1 = 0.0f;
#pragma unroll
        for (int n = 0; n < 8; n++) {
            float p0 = __expf(sc[n][0] - mn0), p1 = __expf(sc[n][1] - mn0);
            float p2 = __expf(sc[n][2] - mn1), p3 = __expf(sc[n][3] - mn1);
            sc[n][0] = p0; sc[n][1] = p1; sc[n][2] = p2; sc[n][3] = p3;
            rs0 += p0 + p1; rs1 += p2 + p3;
        }
        rs0 += __shfl_xor_sync(0xffffffffu, rs0, 1);
        rs0 += __shfl_xor_sync(0xffffffffu, rs0, 2);
        rs1 += __shfl_xor_sync(0xffffffffu, rs1, 1);
        rs1 += __shfl_xor_sync(0xffffffffu, rs1, 2);
        l0 = l0 * a0 + rs0;
        l1 = l1 * a1 + rs1;

#pragma unroll
        for (int n = 0; n < 16; n++) {
            o[n][0] *= a0; o[n][1] *= a0;
            o[n][2] *= a1; o[n][3] *= a1;
        }

        // pack P -> bf16 hi/lo A-fragments (c-layout == A-layout identity)
        uint32_t ph0[8], pl0[8], ph1[8], pl1[8];
#pragma unroll
        for (int n = 0; n < 8; n++) {
            split2(sc[n][0], sc[n][1], ph0[n], pl0[n]);
            split2(sc[n][2], sc[n][3], ph1[n], pl1[n]);
        }

        // ---- P @ V: 3-product split bf16 ----
#pragma unroll
        for (int ks = 0; ks < 4; ++ks) {
            uint32_t aPh[4] = {ph0[2 * ks], ph1[2 * ks], ph0[2 * ks + 1], ph1[2 * ks + 1]};
            uint32_t aPl[4] = {pl0[2 * ks], pl1[2 * ks], pl0[2 * ks + 1], pl1[2 * ks + 1]};
#pragma unroll
            for (int ng = 0; ng < 8; ++ng) {
                uint32_t vh[4], vl[4];
                const uint32_t off = (uint32_t)(ks * 4352 + ng * 32);
                LDSM4T(vh[0], vh[1], vh[2], vh[3], vb0 + off);
                LDSM4T(vl[0], vl[1], vl[2], vl[3], vb1 + off);
                MMA(o[2 * ng], aPh, vh[0], vh[1]);
                MMA(o[2 * ng], aPh, vl[0], vl[1]);
                MMA(o[2 * ng], aPl, vh[0], vh[1]);
                MMA(o[2 * ng + 1], aPh, vh[2], vh[3]);
                MMA(o[2 * ng + 1], aPh, vl[2], vl[3]);
                MMA(o[2 * ng + 1], aPl, vh[2], vh[3]);
            }
        }
    }

    // ---- finalize: divide by l, write split planes for the WO GEMM ----
    const float inv0 = 1.0f / l0, inv1 = 1.0f / l1;
    const int b = bh >> 4, h = bh & 15;
    const size_t row0 = (size_t)(b * 2048 + i0) * 2048 + h * 128;
    const size_t row1 = row0 + (size_t)8 * 2048;
#pragma unroll
    for (int n = 0; n < 16; n++) {
        const int c = n * 8 + 2 * t4;
        uint32_t hh, ll;
        split2(o[n][0] * inv0, o[n][1] * inv0, hh, ll);
        *(uint32_t*)&g_ah[row0 + c] = hh;
        *(uint32_t*)&g_al[row0 + c] = ll;
        split2(o[n][2] * inv1, o[n][3] * inv1, hh, ll);
        *(uint32_t*)&g_ah[row1 + c] = hh;
        *(uint32_t*)&g_al[row1 + c] = ll;
    }
}

// ---------------- launch -------------------------------------------------
extern "C" void kernel_launch(void* const* d_in, const int* in_sizes, int n_in,
                              void* d_out, int out_size) {
    const float* x  = (const float*)d_in[0];
    const float* wq = (const float*)d_in[1];
    const float* wk = (const float*)d_in[2];
    const float* wv = (const float*)d_in[3];
    const float* wo = (const float*)d_in[4];
    float* out = (float*)d_out;

    cudaFuncSetAttribute(attn_mma, cudaFuncAttributeMaxDynamicSharedMemorySize,
                         ATT_SMEM_BYTES);
    cudaFuncSetAttribute(gemm_mma<1>, cudaFuncAttributeMaxDynamicSharedMemorySize,
                         GEMM_SMEM_BYTES);
    cudaFuncSetAttribute(gemm_mma<0>, cudaFuncAttributeMaxDynamicSharedMemorySize,
                         GEMM_SMEM_BYTES);

    rope_tab_kernel<<<512, 256>>>();
    split_all<<<SPLIT_ALL_BLOCKS, 256>>>(x, wq, wk, wv, wo);

    gemm_mma<1><<<dim3(48, 32), 256, GEMM_SMEM_BYTES>>>(nullptr);
    attn_mma<<<dim3(32, 16), 256, ATT_SMEM_BYTES>>>();
    gemm_mma<0><<<dim3(16, 32), 256, GEMM_SMEM_BYTES>>>(out);
}